// round 3
// baseline (speedup 1.0000x reference)
#include <cuda_runtime.h>
#include <cuda_bf16.h>
#include <cstddef>

// Problem constants
#define TT 64
#define BB 64
#define NHID 1024
#define NB 4
#define BS 256
#define G4 4096            // NB * 4*BS gate width per (t,b)
#define NTOK 32000
#define DKq 16
#define NLAYERS 2

// ---------------- scratch (static __device__ arrays; no allocations) -------
__device__ float g_xa[(size_t)TT * BB * NHID];     // 16 MB
__device__ float g_xb[(size_t)TT * BB * NHID];     // 16 MB
__device__ float g_gates[(size_t)TT * BB * G4];    // 64 MB
__device__ float g_h[BB * NHID];
__device__ float g_c[BB * NHID];

__device__ __forceinline__ float sigf(float x) { return 1.f / (1.f + expf(-x)); }

// ---------------- embedding gather ----------------
__global__ void embed_kernel(const int* __restrict__ tokens,
                             const float* __restrict__ embW,
                             float* __restrict__ x) {
    int row = blockIdx.x;                       // t*B + b
    int tok = tokens[row];
    const float4* src = (const float4*)&embW[(size_t)tok * NHID];
    float4* dst = (float4*)&x[(size_t)row * NHID];
    dst[threadIdx.x] = src[threadIdx.x];        // 256 threads * float4 = 1024 floats
}

// ---------------- C[M,N] = A[M,K] * B[N,K]^T (+bias1[n] +bias2[n]) ---------
// 128x128 tile, 256 threads, 8x8 per thread, K-chunk 8. All dims divisible.
__global__ void sgemm_abt_kernel(const float* __restrict__ A,
                                 const float* __restrict__ B,
                                 float* __restrict__ C,
                                 int M, int N, int K,
                                 const float* __restrict__ bias1,
                                 const float* __restrict__ bias2) {
    __shared__ float As[8][128];
    __shared__ float Bs[8][128];
    const int tid = threadIdx.x;
    const int m0 = blockIdx.y * 128;
    const int n0 = blockIdx.x * 128;
    const int tx = tid & 15;        // 0..15  -> col group
    const int ty = tid >> 4;        // 0..15  -> row group
    const int lr = tid >> 1;        // load row 0..127
    const int lk = (tid & 1) * 4;   // load k offset 0 or 4

    float acc[8][8];
#pragma unroll
    for (int i = 0; i < 8; i++)
#pragma unroll
        for (int j = 0; j < 8; j++) acc[i][j] = 0.f;

    for (int kc = 0; kc < K; kc += 8) {
        float4 av = *(const float4*)&A[(size_t)(m0 + lr) * K + kc + lk];
        float4 bv = *(const float4*)&B[(size_t)(n0 + lr) * K + kc + lk];
        As[lk + 0][lr] = av.x; As[lk + 1][lr] = av.y;
        As[lk + 2][lr] = av.z; As[lk + 3][lr] = av.w;
        Bs[lk + 0][lr] = bv.x; Bs[lk + 1][lr] = bv.y;
        Bs[lk + 2][lr] = bv.z; Bs[lk + 3][lr] = bv.w;
        __syncthreads();
#pragma unroll
        for (int k = 0; k < 8; k++) {
            float4 a0 = *(const float4*)&As[k][ty * 8];
            float4 a1 = *(const float4*)&As[k][ty * 8 + 4];
            float4 b0 = *(const float4*)&Bs[k][tx * 8];
            float4 b1 = *(const float4*)&Bs[k][tx * 8 + 4];
            float a[8] = {a0.x, a0.y, a0.z, a0.w, a1.x, a1.y, a1.z, a1.w};
            float bb[8] = {b0.x, b0.y, b0.z, b0.w, b1.x, b1.y, b1.z, b1.w};
#pragma unroll
            for (int i = 0; i < 8; i++)
#pragma unroll
                for (int j = 0; j < 8; j++) acc[i][j] += a[i] * bb[j];
        }
        __syncthreads();
    }

    float bs[8];
#pragma unroll
    for (int j = 0; j < 8; j++) {
        int col = n0 + tx * 8 + j;
        float v = 0.f;
        if (bias1) v += bias1[col];
        if (bias2) v += bias2[col];
        bs[j] = v;
    }
#pragma unroll
    for (int i = 0; i < 8; i++) {
        size_t row = (size_t)(m0 + ty * 8 + i);
        float4 o0 = make_float4(acc[i][0] + bs[0], acc[i][1] + bs[1],
                                acc[i][2] + bs[2], acc[i][3] + bs[3]);
        float4 o1 = make_float4(acc[i][4] + bs[4], acc[i][5] + bs[5],
                                acc[i][6] + bs[6], acc[i][7] + bs[7]);
        *(float4*)&C[row * N + n0 + tx * 8]     = o0;
        *(float4*)&C[row * N + n0 + tx * 8 + 4] = o1;
    }
}

// ---------------- per-timestep: gates_t[b, n*1024+g] += h[b,n,:] . Whh[n,g,:]
// grid = (128, 4): x = group of 8 gate-cols, y = block n. 256 threads = 8 warps.
__global__ void hh_gemm_kernel(const float* __restrict__ h,
                               const float* __restrict__ Whh,
                               float* __restrict__ gates_t) {
    __shared__ float hs[64 * 64];               // [kk][b]
    const int n = blockIdx.y;
    const int warp = threadIdx.x >> 5;
    const int lane = threadIdx.x & 31;
    const int g = blockIdx.x * 8 + warp;        // 0..1023
    const float* wrow = Whh + (size_t)(n * 1024 + g) * BS;

    float acc0 = 0.f, acc1 = 0.f;
    for (int kc = 0; kc < BS; kc += 64) {
        __syncthreads();
#pragma unroll
        for (int i = 0; i < 4; i++) {
            int e = threadIdx.x + i * 256;      // 0..1023 float4 slots
            int b = e >> 4;
            int kk4 = (e & 15) << 2;
            float4 v = *(const float4*)&h[(size_t)b * NHID + n * BS + kc + kk4];
            hs[(kk4 + 0) * 64 + b] = v.x;
            hs[(kk4 + 1) * 64 + b] = v.y;
            hs[(kk4 + 2) * 64 + b] = v.z;
            hs[(kk4 + 3) * 64 + b] = v.w;
        }
        __syncthreads();
        const float4* wp = (const float4*)(wrow + kc);
#pragma unroll
        for (int k4 = 0; k4 < 16; k4++) {
            float4 w = wp[k4];
            int kk = k4 * 4;
            acc0 += w.x * hs[(kk + 0) * 64 + lane];
            acc0 += w.y * hs[(kk + 1) * 64 + lane];
            acc0 += w.z * hs[(kk + 2) * 64 + lane];
            acc0 += w.w * hs[(kk + 3) * 64 + lane];
            acc1 += w.x * hs[(kk + 0) * 64 + lane + 32];
            acc1 += w.y * hs[(kk + 1) * 64 + lane + 32];
            acc1 += w.z * hs[(kk + 2) * 64 + lane + 32];
            acc1 += w.w * hs[(kk + 3) * 64 + lane + 32];
        }
    }
    gates_t[(size_t)lane * G4 + n * 1024 + g]        += acc0;
    gates_t[(size_t)(lane + 32) * G4 + n * 1024 + g] += acc1;
}

// ---------------- fused LSTM elementwise + block-MHA + LayerNorm -----------
// One block per batch element b. 256 threads.
__global__ void lstm_mha_kernel(const float* __restrict__ gates_t,
                                float* __restrict__ h, float* __restrict__ c,
                                const float* __restrict__ wq, const float* __restrict__ bq,
                                const float* __restrict__ wk, const float* __restrict__ bk,
                                const float* __restrict__ wv, const float* __restrict__ bv,
                                const float* __restrict__ wfc, const float* __restrict__ bfc,
                                const float* __restrict__ lng, const float* __restrict__ lnb,
                                float* __restrict__ xout) {
    __shared__ float hl[NB][BS];
    __shared__ float res[NB][BS];
    __shared__ float qs[NB][DKq], ks[NB][DKq], vs[NB][DKq];
    __shared__ float scores[NB][NB], attn[NB][NB], av[NB][DKq];
    __shared__ float redS[8], redS2[8];

    const int b = blockIdx.x;
    const int tid = threadIdx.x;
    const float* gb = gates_t + (size_t)b * G4;

    // LSTM cell
#pragma unroll
    for (int n = 0; n < NB; n++) {
        float ig = gb[n * 1024 + tid];
        float fg = gb[n * 1024 + 256 + tid];
        float gg = gb[n * 1024 + 512 + tid];
        float og = gb[n * 1024 + 768 + tid];
        float co = c[(size_t)b * NHID + n * BS + tid];
        float cn = sigf(fg) * co + sigf(ig) * tanhf(gg);
        c[(size_t)b * NHID + n * BS + tid] = cn;
        hl[n][tid] = sigf(og) * tanhf(cn);
    }
    __syncthreads();

    // q/k/v projections: 192 threads, one (proj, n, d) each, dot over 256
    if (tid < 192) {
        int p = tid / 64, r = tid % 64, n = r >> 4, d = r & 15;
        const float* W = (p == 0 ? wq : (p == 1 ? wk : wv)) + (size_t)d * BS;
        float s = (p == 0 ? bq : (p == 1 ? bk : bv))[d];
        const float4* W4 = (const float4*)W;
        const float4* H4 = (const float4*)hl[n];
#pragma unroll 4
        for (int k4 = 0; k4 < BS / 4; k4++) {
            float4 w = W4[k4];
            float4 hh = H4[k4];
            s += w.x * hh.x + w.y * hh.y + w.z * hh.z + w.w * hh.w;
        }
        if (p == 0) qs[n][d] = s;
        else if (p == 1) ks[n][d] = s;
        else vs[n][d] = s;
    }
    __syncthreads();

    // scores [4x4]
    if (tid < 16) {
        int n = tid >> 2, m = tid & 3;
        float s = 0.f;
#pragma unroll
        for (int d = 0; d < DKq; d++) s += qs[n][d] * ks[m][d];
        scores[n][m] = s * 0.25f;       // 1/sqrt(16)
    }
    __syncthreads();
    if (tid < 4) {
        float s0 = scores[tid][0], s1 = scores[tid][1];
        float s2 = scores[tid][2], s3 = scores[tid][3];
        float mx = fmaxf(fmaxf(s0, s1), fmaxf(s2, s3));
        float e0 = expf(s0 - mx), e1 = expf(s1 - mx);
        float e2 = expf(s2 - mx), e3 = expf(s3 - mx);
        float inv = 1.f / (e0 + e1 + e2 + e3);
        attn[tid][0] = e0 * inv; attn[tid][1] = e1 * inv;
        attn[tid][2] = e2 * inv; attn[tid][3] = e3 * inv;
    }
    __syncthreads();
    if (tid < 64) {
        int n = tid >> 4, d = tid & 15;
        av[n][d] = attn[n][0] * vs[0][d] + attn[n][1] * vs[1][d] +
                   attn[n][2] * vs[2][d] + attn[n][3] * vs[3][d];
    }
    __syncthreads();

    // out projection + residual
    {
        float bf = bfc[tid];
        float w[DKq];
        const float4* wr = (const float4*)&wfc[(size_t)tid * DKq];
#pragma unroll
        for (int q4 = 0; q4 < 4; q4++) {
            float4 v = wr[q4];
            w[q4 * 4 + 0] = v.x; w[q4 * 4 + 1] = v.y;
            w[q4 * 4 + 2] = v.z; w[q4 * 4 + 3] = v.w;
        }
#pragma unroll
        for (int n = 0; n < NB; n++) {
            float o = bf;
#pragma unroll
            for (int d = 0; d < DKq; d++) o += av[n][d] * w[d];
            res[n][tid] = o + hl[n][tid];
        }
    }
    __syncthreads();

    // LayerNorm per (b, n)
    const int wid = tid >> 5, lane = tid & 31;
    float gsc = lng[tid], gof = lnb[tid];
    for (int n = 0; n < NB; n++) {
        float v = res[n][tid];
        float s = v, s2 = v * v;
#pragma unroll
        for (int o = 16; o; o >>= 1) {
            s  += __shfl_down_sync(0xffffffffu, s, o);
            s2 += __shfl_down_sync(0xffffffffu, s2, o);
        }
        if (lane == 0) { redS[wid] = s; redS2[wid] = s2; }
        __syncthreads();
        if (tid == 0) {
            float S = 0.f, S2 = 0.f;
#pragma unroll
            for (int w2 = 0; w2 < 8; w2++) { S += redS[w2]; S2 += redS2[w2]; }
            redS[0] = S * (1.f / 256.f);
            redS2[0] = S2 * (1.f / 256.f);
        }
        __syncthreads();
        float mu = redS[0];
        float var = redS2[0] - mu * mu;
        float y = (v - mu) * rsqrtf(var + 1e-5f) * gsc + gof;
        h[(size_t)b * NHID + n * BS + tid] = y;
        xout[(size_t)b * NHID + n * BS + tid] = y;
        __syncthreads();
    }
}

// ---------------- host orchestration ----------------
extern "C" void kernel_launch(void* const* d_in, const int* in_sizes, int n_in,
                              void* d_out, int out_size) {
    (void)in_sizes; (void)n_in; (void)out_size;
    const int*   tokens = (const int*)d_in[0];
    const float* h0     = (const float*)d_in[1];
    const float* c0     = (const float*)d_in[2];
    const float* embW   = (const float*)d_in[3];
    const float* Wih    = (const float*)d_in[4];
    const float* Whh    = (const float*)d_in[5];
    const float* bih    = (const float*)d_in[6];
    const float* bhh    = (const float*)d_in[7];
    const float* wq     = (const float*)d_in[8];
    const float* bq     = (const float*)d_in[9];
    const float* wk     = (const float*)d_in[10];
    const float* bk     = (const float*)d_in[11];
    const float* wv     = (const float*)d_in[12];
    const float* bv     = (const float*)d_in[13];
    const float* wfc    = (const float*)d_in[14];
    const float* bfc    = (const float*)d_in[15];
    const float* lng    = (const float*)d_in[16];
    const float* lnb    = (const float*)d_in[17];
    const float* decW   = (const float*)d_in[18];
    const float* decb   = (const float*)d_in[19];
    float* out = (float*)d_out;

    float *xa, *xb, *gates, *hbuf, *cbuf;
    cudaGetSymbolAddress((void**)&xa, g_xa);
    cudaGetSymbolAddress((void**)&xb, g_xb);
    cudaGetSymbolAddress((void**)&gates, g_gates);
    cudaGetSymbolAddress((void**)&hbuf, g_h);
    cudaGetSymbolAddress((void**)&cbuf, g_c);

    const size_t stateN = (size_t)BB * NHID;              // 65536
    const size_t decN   = (size_t)TT * BB * NTOK;         // 131072000

    // 1) embedding -> xa
    embed_kernel<<<TT * BB, 256>>>(tokens, embW, xa);

    float* xin = xa;
    float* xo  = xb;
    for (int l = 0; l < NLAYERS; l++) {
        // 2a) gate pre-activations for ALL timesteps: gates = x @ Wih^T + b_ih + b_hh
        sgemm_abt_kernel<<<dim3(G4 / 128, (TT * BB) / 128), 256>>>(
            xin, Wih + (size_t)l * G4 * NHID, gates,
            TT * BB, G4, NHID, bih + (size_t)l * G4, bhh + (size_t)l * G4);

        cudaMemcpyAsync(hbuf, h0 + (size_t)l * stateN, stateN * sizeof(float),
                        cudaMemcpyDeviceToDevice, 0);
        cudaMemcpyAsync(cbuf, c0 + (size_t)l * stateN, stateN * sizeof(float),
                        cudaMemcpyDeviceToDevice, 0);

        // 2b) recurrence
        for (int t = 0; t < TT; t++) {
            float* gt = gates + (size_t)t * BB * G4;
            hh_gemm_kernel<<<dim3(128, NB), 256>>>(
                hbuf, Whh + (size_t)l * NB * 1024 * BS, gt);
            lstm_mha_kernel<<<BB, 256>>>(
                gt, hbuf, cbuf, wq, bq, wk, bk, wv, bv, wfc, bfc, lng, lnb,
                xo + (size_t)t * BB * NHID);
        }

        // 2c) final states into output tail
        cudaMemcpyAsync(out + decN + (size_t)l * stateN, hbuf,
                        stateN * sizeof(float), cudaMemcpyDeviceToDevice, 0);
        cudaMemcpyAsync(out + decN + 2 * stateN + (size_t)l * stateN, cbuf,
                        stateN * sizeof(float), cudaMemcpyDeviceToDevice, 0);

        float* tmp = xin; xin = xo; xo = tmp;
    }

    // 3) decoder: out[t,b,:] = x @ decW^T + decb
    sgemm_abt_kernel<<<dim3(NTOK / 128, (TT * BB) / 128), 256>>>(
        xin, decW, out, TT * BB, NTOK, NHID, decb, nullptr);
}

// round 6
// speedup vs baseline: 1.4317x; 1.4317x over previous
#include <cuda_runtime.h>
#include <cuda_bf16.h>
#include <cstdint>
#include <cstddef>

// Problem constants
#define TT 64
#define BB 64
#define NHID 1024
#define NB 4
#define BS 256
#define G4 4096            // NB * 4*BS gate width per (t,b)
#define NTOK 32000
#define DKq 16
#define NLAYERS 2

// ---------------- scratch (static __device__ arrays; no allocations) -------
__device__ float g_xa[(size_t)TT * BB * NHID];     // 16 MB
__device__ float g_xb[(size_t)TT * BB * NHID];     // 16 MB
__device__ float g_gates[(size_t)TT * BB * G4];    // 64 MB
__device__ float g_h[BB * NHID];
__device__ float g_c[BB * NHID];

__device__ __forceinline__ float sigf(float x) { return 1.f / (1.f + expf(-x)); }

// ---------------- embedding gather ----------------
__global__ void embed_kernel(const int* __restrict__ tokens,
                             const float* __restrict__ embW,
                             float* __restrict__ x) {
    int row = blockIdx.x;                       // t*B + b
    int tok = tokens[row];
    const float4* src = (const float4*)&embW[(size_t)tok * NHID];
    float4* dst = (float4*)&x[(size_t)row * NHID];
    dst[threadIdx.x] = src[threadIdx.x];
}

// ===================== common MMA helpers =====================
#define LDSM4(R, ptr) do {                                                   \
    uint32_t _a = (uint32_t)__cvta_generic_to_shared(ptr);                   \
    asm volatile("ldmatrix.sync.aligned.m8n8.x4.shared.b16 {%0,%1,%2,%3},[%4];" \
        : "=r"((R)[0]), "=r"((R)[1]), "=r"((R)[2]), "=r"((R)[3]) : "r"(_a)); \
} while (0)

#define MMA16816(c, a, b0v, b1v) asm volatile(                               \
    "mma.sync.aligned.m16n8k16.row.col.f32.bf16.bf16.f32 "                   \
    "{%0,%1,%2,%3},{%4,%5,%6,%7},{%8,%9},{%0,%1,%2,%3};\n"                   \
    : "+f"((c)[0]), "+f"((c)[1]), "+f"((c)[2]), "+f"((c)[3])                 \
    : "r"((a)[0]), "r"((a)[1]), "r"((a)[2]), "r"((a)[3]),                    \
      "r"(b0v), "r"(b1v))

#define MMATF32(c, a, b0v, b1v) asm volatile(                                \
    "mma.sync.aligned.m16n8k8.row.col.f32.tf32.tf32.f32 "                    \
    "{%0,%1,%2,%3},{%4,%5,%6,%7},{%8,%9},{%0,%1,%2,%3};\n"                   \
    : "+f"((c)[0]), "+f"((c)[1]), "+f"((c)[2]), "+f"((c)[3])                 \
    : "r"((a)[0]), "r"((a)[1]), "r"((a)[2]), "r"((a)[3]),                    \
      "r"(b0v), "r"(b1v))

__device__ __forceinline__ uint32_t f2tf32(float x) {
    uint32_t r;
    asm("cvt.rna.tf32.f32 %0, %1;" : "=r"(r) : "f"(x));
    return r;
}
__device__ __forceinline__ float tf32f(uint32_t r) {
    return __uint_as_float(r);
}

// ============ bf16-split tensor-core GEMM (decoder): C = A·Bᵀ (+bias) ======
// Block tile 128x128x32, 256 threads = 8 warps, warp tile 32x64.
__global__ __launch_bounds__(256, 1)
void mma_gemm_abt(const float* __restrict__ A, const float* __restrict__ B,
                  float* __restrict__ C, int M, int N, int K,
                  const float* __restrict__ bias1, const float* __restrict__ bias2) {
    __shared__ alignas(16) __nv_bfloat16 Ahi[128][40];
    __shared__ alignas(16) __nv_bfloat16 Alo[128][40];
    __shared__ alignas(16) __nv_bfloat16 Bhi[128][40];
    __shared__ alignas(16) __nv_bfloat16 Blo[128][40];

    const int tid  = threadIdx.x;
    const int warp = tid >> 5, lane = tid & 31;
    const int wm = warp >> 1, wn = warp & 1;
    const int m0 = blockIdx.x * 128;                // x = M tiles (fast) for B L2 reuse
    const int n0 = blockIdx.y * 128;

    float c_[2][8][4];
#pragma unroll
    for (int i = 0; i < 2; i++)
#pragma unroll
        for (int j = 0; j < 8; j++)
#pragma unroll
            for (int k = 0; k < 4; k++) c_[i][j][k] = 0.f;

    float4 pa[4], pb[4];
    int prow[4], pcol[4];
#pragma unroll
    for (int f = 0; f < 4; f++) {
        int id = f * 256 + tid;
        prow[f] = id >> 3;
        pcol[f] = (id & 7) * 4;
    }

    const int nk = K >> 5;
#pragma unroll
    for (int f = 0; f < 4; f++) {
        pa[f] = *(const float4*)&A[(size_t)(m0 + prow[f]) * K + pcol[f]];
        pb[f] = *(const float4*)&B[(size_t)(n0 + prow[f]) * K + pcol[f]];
    }

    for (int kc = 0; kc < nk; kc++) {
        __syncthreads();
#pragma unroll
        for (int f = 0; f < 4; f++) {
            int r = prow[f], cc = pcol[f];
            float4 va = pa[f], vb = pb[f];
            __nv_bfloat16 ax = __float2bfloat16(va.x), ay = __float2bfloat16(va.y);
            __nv_bfloat16 az = __float2bfloat16(va.z), aw = __float2bfloat16(va.w);
            __nv_bfloat16 lx = __float2bfloat16(va.x - __bfloat162float(ax));
            __nv_bfloat16 ly = __float2bfloat16(va.y - __bfloat162float(ay));
            __nv_bfloat16 lz = __float2bfloat16(va.z - __bfloat162float(az));
            __nv_bfloat16 lw = __float2bfloat16(va.w - __bfloat162float(aw));
            __nv_bfloat162 t;
            t.x = ax; t.y = ay; *(__nv_bfloat162*)&Ahi[r][cc + 0] = t;
            t.x = az; t.y = aw; *(__nv_bfloat162*)&Ahi[r][cc + 2] = t;
            t.x = lx; t.y = ly; *(__nv_bfloat162*)&Alo[r][cc + 0] = t;
            t.x = lz; t.y = lw; *(__nv_bfloat162*)&Alo[r][cc + 2] = t;

            __nv_bfloat16 bx = __float2bfloat16(vb.x), by = __float2bfloat16(vb.y);
            __nv_bfloat16 bz = __float2bfloat16(vb.z), bw = __float2bfloat16(vb.w);
            __nv_bfloat16 mx = __float2bfloat16(vb.x - __bfloat162float(bx));
            __nv_bfloat16 my = __float2bfloat16(vb.y - __bfloat162float(by));
            __nv_bfloat16 mz = __float2bfloat16(vb.z - __bfloat162float(bz));
            __nv_bfloat16 mw = __float2bfloat16(vb.w - __bfloat162float(bw));
            t.x = bx; t.y = by; *(__nv_bfloat162*)&Bhi[r][cc + 0] = t;
            t.x = bz; t.y = bw; *(__nv_bfloat162*)&Bhi[r][cc + 2] = t;
            t.x = mx; t.y = my; *(__nv_bfloat162*)&Blo[r][cc + 0] = t;
            t.x = mz; t.y = mw; *(__nv_bfloat162*)&Blo[r][cc + 2] = t;
        }
        __syncthreads();

        if (kc + 1 < nk) {
            int kb = (kc + 1) << 5;
#pragma unroll
            for (int f = 0; f < 4; f++) {
                pa[f] = *(const float4*)&A[(size_t)(m0 + prow[f]) * K + kb + pcol[f]];
                pb[f] = *(const float4*)&B[(size_t)(n0 + prow[f]) * K + kb + pcol[f]];
            }
        }

#pragma unroll
        for (int ks = 0; ks < 2; ks++) {
            const int kb = ks * 16;
            uint32_t ah[2][4], al[2][4], bh[4][4], bl[4][4];
#pragma unroll
            for (int mt = 0; mt < 2; mt++) {
                int row = wm * 32 + mt * 16 + (lane & 15);
                int ko  = kb + ((lane >> 4) << 3);
                LDSM4(ah[mt], &Ahi[row][ko]);
                LDSM4(al[mt], &Alo[row][ko]);
            }
#pragma unroll
            for (int p = 0; p < 4; p++) {
                int row = wn * 64 + p * 16 + ((lane >> 4) << 3) + (lane & 7);
                int ko  = kb + (((lane >> 3) & 1) << 3);
                LDSM4(bh[p], &Bhi[row][ko]);
                LDSM4(bl[p], &Blo[row][ko]);
            }
#pragma unroll
            for (int mt = 0; mt < 2; mt++)
#pragma unroll
                for (int nt = 0; nt < 8; nt++) {
                    int p = nt >> 1, o = (nt & 1) * 2;
                    MMA16816(c_[mt][nt], ah[mt], bh[p][o], bh[p][o + 1]);
                    MMA16816(c_[mt][nt], ah[mt], bl[p][o], bl[p][o + 1]);
                    MMA16816(c_[mt][nt], al[mt], bh[p][o], bh[p][o + 1]);
                }
        }
    }

    const int g = lane >> 2, t2 = (lane & 3) * 2;
#pragma unroll
    for (int mt = 0; mt < 2; mt++) {
#pragma unroll
        for (int nt = 0; nt < 8; nt++) {
            int row = m0 + wm * 32 + mt * 16 + g;
            int col = n0 + wn * 64 + nt * 8 + t2;
            float b0a = 0.f, b1a = 0.f;
            if (bias1) { b0a += bias1[col]; b1a += bias1[col + 1]; }
            if (bias2) { b0a += bias2[col]; b1a += bias2[col + 1]; }
            float2 v0 = make_float2(c_[mt][nt][0] + b0a, c_[mt][nt][1] + b1a);
            float2 v1 = make_float2(c_[mt][nt][2] + b0a, c_[mt][nt][3] + b1a);
            *(float2*)&C[(size_t)row * N + col]       = v0;
            *(float2*)&C[(size_t)(row + 8) * N + col] = v1;
        }
    }
}

// ============ tf32-split tensor-core GEMM (ih gates): C = A·Bᵀ (+bias) =====
// Per-product error ~2^-21 — safe inside the recurrence.
// Block tile 128x128x16, 256 threads = 8 warps, warp tile 32x64.
__global__ __launch_bounds__(256)
void mma_gemm_abt_tf32(const float* __restrict__ A, const float* __restrict__ B,
                       float* __restrict__ C, int M, int N, int K,
                       const float* __restrict__ bias1, const float* __restrict__ bias2) {
    __shared__ alignas(16) uint32_t Ahi[128][20];
    __shared__ alignas(16) uint32_t Alo[128][20];
    __shared__ alignas(16) uint32_t Bhi[128][20];
    __shared__ alignas(16) uint32_t Blo[128][20];

    const int tid  = threadIdx.x;
    const int warp = tid >> 5, lane = tid & 31;
    const int wm = warp >> 1, wn = warp & 1;
    const int gq = lane >> 2, t4 = lane & 3;
    const int m0 = blockIdx.x * 128;
    const int n0 = blockIdx.y * 128;

    float c_[2][8][4];
#pragma unroll
    for (int i = 0; i < 2; i++)
#pragma unroll
        for (int j = 0; j < 8; j++)
#pragma unroll
            for (int k = 0; k < 4; k++) c_[i][j][k] = 0.f;

    // tile 128x16 fp32 per operand = 512 float4; 2 per thread
    float4 pa[2], pb[2];
    int prow[2], pcol[2];
#pragma unroll
    for (int f = 0; f < 2; f++) {
        int id = f * 256 + tid;
        prow[f] = id >> 2;
        pcol[f] = (id & 3) * 4;
    }

    const int nk = K >> 4;
#pragma unroll
    for (int f = 0; f < 2; f++) {
        pa[f] = *(const float4*)&A[(size_t)(m0 + prow[f]) * K + pcol[f]];
        pb[f] = *(const float4*)&B[(size_t)(n0 + prow[f]) * K + pcol[f]];
    }

    for (int kc = 0; kc < nk; kc++) {
        __syncthreads();
#pragma unroll
        for (int f = 0; f < 2; f++) {
            int r = prow[f], cc = pcol[f];
            float4 va = pa[f], vb = pb[f];
            uint32_t h0 = f2tf32(va.x), h1 = f2tf32(va.y);
            uint32_t h2 = f2tf32(va.z), h3 = f2tf32(va.w);
            uint4 hv = make_uint4(h0, h1, h2, h3);
            uint4 lv = make_uint4(f2tf32(va.x - tf32f(h0)), f2tf32(va.y - tf32f(h1)),
                                  f2tf32(va.z - tf32f(h2)), f2tf32(va.w - tf32f(h3)));
            *(uint4*)&Ahi[r][cc] = hv;
            *(uint4*)&Alo[r][cc] = lv;

            h0 = f2tf32(vb.x); h1 = f2tf32(vb.y);
            h2 = f2tf32(vb.z); h3 = f2tf32(vb.w);
            hv = make_uint4(h0, h1, h2, h3);
            lv = make_uint4(f2tf32(vb.x - tf32f(h0)), f2tf32(vb.y - tf32f(h1)),
                            f2tf32(vb.z - tf32f(h2)), f2tf32(vb.w - tf32f(h3)));
            *(uint4*)&Bhi[r][cc] = hv;
            *(uint4*)&Blo[r][cc] = lv;
        }
        __syncthreads();

        if (kc + 1 < nk) {
            int kb = (kc + 1) << 4;
#pragma unroll
            for (int f = 0; f < 2; f++) {
                pa[f] = *(const float4*)&A[(size_t)(m0 + prow[f]) * K + kb + pcol[f]];
                pb[f] = *(const float4*)&B[(size_t)(n0 + prow[f]) * K + kb + pcol[f]];
            }
        }

#pragma unroll
        for (int ks = 0; ks < 2; ks++) {
            const int kb = ks * 8;
            uint32_t ah[2][4], al[2][4], bh[8][2], bl[8][2];
#pragma unroll
            for (int mt = 0; mt < 2; mt++) {
                int rb = wm * 32 + mt * 16;
                ah[mt][0] = Ahi[rb + gq][kb + t4];
                ah[mt][1] = Ahi[rb + 8 + gq][kb + t4];
                ah[mt][2] = Ahi[rb + gq][kb + t4 + 4];
                ah[mt][3] = Ahi[rb + 8 + gq][kb + t4 + 4];
                al[mt][0] = Alo[rb + gq][kb + t4];
                al[mt][1] = Alo[rb + 8 + gq][kb + t4];
                al[mt][2] = Alo[rb + gq][kb + t4 + 4];
                al[mt][3] = Alo[rb + 8 + gq][kb + t4 + 4];
            }
#pragma unroll
            for (int nt = 0; nt < 8; nt++) {
                int bn = wn * 64 + nt * 8 + gq;
                bh[nt][0] = Bhi[bn][kb + t4];
                bh[nt][1] = Bhi[bn][kb + t4 + 4];
                bl[nt][0] = Blo[bn][kb + t4];
                bl[nt][1] = Blo[bn][kb + t4 + 4];
            }
#pragma unroll
            for (int mt = 0; mt < 2; mt++)
#pragma unroll
                for (int nt = 0; nt < 8; nt++) {
                    MMATF32(c_[mt][nt], ah[mt], bh[nt][0], bh[nt][1]);
                    MMATF32(c_[mt][nt], ah[mt], bl[nt][0], bl[nt][1]);
                    MMATF32(c_[mt][nt], al[mt], bh[nt][0], bh[nt][1]);
                }
        }
    }

    const int t2 = t4 * 2;
#pragma unroll
    for (int mt = 0; mt < 2; mt++) {
#pragma unroll
        for (int nt = 0; nt < 8; nt++) {
            int row = m0 + wm * 32 + mt * 16 + gq;
            int col = n0 + wn * 64 + nt * 8 + t2;
            float b0a = 0.f, b1a = 0.f;
            if (bias1) { b0a += bias1[col]; b1a += bias1[col + 1]; }
            if (bias2) { b0a += bias2[col]; b1a += bias2[col + 1]; }
            float2 v0 = make_float2(c_[mt][nt][0] + b0a, c_[mt][nt][1] + b1a);
            float2 v1 = make_float2(c_[mt][nt][2] + b0a, c_[mt][nt][3] + b1a);
            *(float2*)&C[(size_t)row * N + col]       = v0;
            *(float2*)&C[(size_t)(row + 8) * N + col] = v1;
        }
    }
}

// ---------------- per-timestep: gates_t[b, n*1024+g] += h[b,n,:] . Whh[n,g,:]
__global__ void hh_gemm_kernel(const float* __restrict__ h,
                               const float* __restrict__ Whh,
                               float* __restrict__ gates_t) {
    __shared__ float hs[64 * 64];               // [kk][b]
    const int n = blockIdx.y;
    const int warp = threadIdx.x >> 5;
    const int lane = threadIdx.x & 31;
    const int g = blockIdx.x * 8 + warp;        // 0..1023
    const float* wrow = Whh + (size_t)(n * 1024 + g) * BS;

    float acc0 = 0.f, acc1 = 0.f;
    for (int kc = 0; kc < BS; kc += 64) {
        __syncthreads();
#pragma unroll
        for (int i = 0; i < 4; i++) {
            int e = threadIdx.x + i * 256;
            int b = e >> 4;
            int kk4 = (e & 15) << 2;
            float4 v = *(const float4*)&h[(size_t)b * NHID + n * BS + kc + kk4];
            hs[(kk4 + 0) * 64 + b] = v.x;
            hs[(kk4 + 1) * 64 + b] = v.y;
            hs[(kk4 + 2) * 64 + b] = v.z;
            hs[(kk4 + 3) * 64 + b] = v.w;
        }
        __syncthreads();
        const float4* wp = (const float4*)(wrow + kc);
#pragma unroll
        for (int k4 = 0; k4 < 16; k4++) {
            float4 w = wp[k4];
            int kk = k4 * 4;
            acc0 += w.x * hs[(kk + 0) * 64 + lane];
            acc0 += w.y * hs[(kk + 1) * 64 + lane];
            acc0 += w.z * hs[(kk + 2) * 64 + lane];
            acc0 += w.w * hs[(kk + 3) * 64 + lane];
            acc1 += w.x * hs[(kk + 0) * 64 + lane + 32];
            acc1 += w.y * hs[(kk + 1) * 64 + lane + 32];
            acc1 += w.z * hs[(kk + 2) * 64 + lane + 32];
            acc1 += w.w * hs[(kk + 3) * 64 + lane + 32];
        }
    }
    gates_t[(size_t)lane * G4 + n * 1024 + g]        += acc0;
    gates_t[(size_t)(lane + 32) * G4 + n * 1024 + g] += acc1;
}

// ---------------- fused LSTM + block-MHA + LayerNorm (1024 threads) --------
__global__ __launch_bounds__(1024)
void lstm_mha_kernel(const float* __restrict__ gates_t,
                     float* __restrict__ h, float* __restrict__ c,
                     const float* __restrict__ wq, const float* __restrict__ bq,
                     const float* __restrict__ wk, const float* __restrict__ bk,
                     const float* __restrict__ wv, const float* __restrict__ bv,
                     const float* __restrict__ wfc, const float* __restrict__ bfc,
                     const float* __restrict__ lng, const float* __restrict__ lnb,
                     float* __restrict__ xout) {
    __shared__ float hl[NB][BS];
    __shared__ float qs[NB][DKq], ks_[NB][DKq], vs[NB][DKq];
    __shared__ float attn[NB][NB];
    __shared__ float av[NB][DKq];
    __shared__ float red[NB][8], red2[NB][8];

    const int b = blockIdx.x;
    const int tid = threadIdx.x;
    const int n = tid >> 8, ti = tid & 255;
    const int lane = tid & 31;

    // LSTM cell (one element per thread)
    const float* gb = gates_t + (size_t)b * G4 + n * 1024;
    float ig = gb[ti], fg = gb[256 + ti], gg = gb[512 + ti], og = gb[768 + ti];
    float co = c[(size_t)b * NHID + n * BS + ti];
    float cn = sigf(fg) * co + sigf(ig) * tanhf(gg);
    c[(size_t)b * NHID + n * BS + ti] = cn;
    float hv = sigf(og) * tanhf(cn);
    hl[n][ti] = hv;
    __syncthreads();

    // q/k/v projections: 768 threads, each quad does one (p, n, d) dot
    if (tid < 768) {
        int combo = tid >> 2, q = tid & 3;
        int p = combo / 64, r2 = combo % 64, nn = r2 >> 4, d = r2 & 15;
        const float* W = (p == 0 ? wq : (p == 1 ? wk : wv)) + (size_t)d * BS + q * 64;
        const float* H = hl[nn] + q * 64;
        const float4* W4 = (const float4*)W;
        const float4* H4 = (const float4*)H;
        float s = 0.f;
#pragma unroll
        for (int k4 = 0; k4 < 16; k4++) {
            float4 w = W4[k4], hh = H4[k4];
            s += w.x * hh.x + w.y * hh.y + w.z * hh.z + w.w * hh.w;
        }
        s += __shfl_down_sync(0xffffffffu, s, 2);
        s += __shfl_down_sync(0xffffffffu, s, 1);
        if (q == 0) {
            s += (p == 0 ? bq : (p == 1 ? bk : bv))[d];
            if (p == 0) qs[nn][d] = s;
            else if (p == 1) ks_[nn][d] = s;
            else vs[nn][d] = s;
        }
    }
    __syncthreads();

    if (tid < 16) {
        int nn = tid >> 2, m = tid & 3;
        float s = 0.f;
#pragma unroll
        for (int d = 0; d < DKq; d++) s += qs[nn][d] * ks_[m][d];
        attn[nn][m] = s * 0.25f;       // 1/sqrt(16)
    }
    __syncthreads();
    if (tid < 4) {
        float s0 = attn[tid][0], s1 = attn[tid][1];
        float s2 = attn[tid][2], s3 = attn[tid][3];
        float mx = fmaxf(fmaxf(s0, s1), fmaxf(s2, s3));
        float e0 = expf(s0 - mx), e1 = expf(s1 - mx);
        float e2 = expf(s2 - mx), e3 = expf(s3 - mx);
        float inv = 1.f / (e0 + e1 + e2 + e3);
        attn[tid][0] = e0 * inv; attn[tid][1] = e1 * inv;
        attn[tid][2] = e2 * inv; attn[tid][3] = e3 * inv;
    }
    __syncthreads();
    if (tid < 64) {
        int nn = tid >> 4, d = tid & 15;
        av[nn][d] = attn[nn][0] * vs[0][d] + attn[nn][1] * vs[1][d] +
                    attn[nn][2] * vs[2][d] + attn[nn][3] * vs[3][d];
    }
    __syncthreads();

    // out projection + residual
    float w[DKq];
    const float4* wr = (const float4*)&wfc[(size_t)ti * DKq];
#pragma unroll
    for (int q4 = 0; q4 < 4; q4++) {
        float4 v = wr[q4];
        w[q4 * 4 + 0] = v.x; w[q4 * 4 + 1] = v.y;
        w[q4 * 4 + 2] = v.z; w[q4 * 4 + 3] = v.w;
    }
    float o = bfc[ti];
#pragma unroll
    for (int d = 0; d < DKq; d++) o += av[n][d] * w[d];
    float v = o + hv;

    // LayerNorm over the 256-thread group of each n (all 4 in parallel)
    float s = v, s2 = v * v;
#pragma unroll
    for (int off = 16; off; off >>= 1) {
        s  += __shfl_down_sync(0xffffffffu, s, off);
        s2 += __shfl_down_sync(0xffffffffu, s2, off);
    }
    int gw = (tid >> 5) & 7;
    if (lane == 0) { red[n][gw] = s; red2[n][gw] = s2; }
    __syncthreads();
    if (ti == 0) {
        float S = 0.f, S2 = 0.f;
#pragma unroll
        for (int w2 = 0; w2 < 8; w2++) { S += red[n][w2]; S2 += red2[n][w2]; }
        red[n][0]  = S * (1.f / 256.f);
        red2[n][0] = S2 * (1.f / 256.f);
    }
    __syncthreads();
    float mu = red[n][0];
    float var = red2[n][0] - mu * mu;
    float y = (v - mu) * rsqrtf(var + 1e-5f) * lng[ti] + lnb[ti];
    h[(size_t)b * NHID + n * BS + ti] = y;
    xout[(size_t)b * NHID + n * BS + ti] = y;
}

// ---------------- host orchestration ----------------
extern "C" void kernel_launch(void* const* d_in, const int* in_sizes, int n_in,
                              void* d_out, int out_size) {
    (void)in_sizes; (void)n_in; (void)out_size;
    const int*   tokens = (const int*)d_in[0];
    const float* h0     = (const float*)d_in[1];
    const float* c0     = (const float*)d_in[2];
    const float* embW   = (const float*)d_in[3];
    const float* Wih    = (const float*)d_in[4];
    const float* Whh    = (const float*)d_in[5];
    const float* bih    = (const float*)d_in[6];
    const float* bhh    = (const float*)d_in[7];
    const float* wq     = (const float*)d_in[8];
    const float* bq     = (const float*)d_in[9];
    const float* wk     = (const float*)d_in[10];
    const float* bk     = (const float*)d_in[11];
    const float* wv     = (const float*)d_in[12];
    const float* bv     = (const float*)d_in[13];
    const float* wfc    = (const float*)d_in[14];
    const float* bfc    = (const float*)d_in[15];
    const float* lng    = (const float*)d_in[16];
    const float* lnb    = (const float*)d_in[17];
    const float* decW   = (const float*)d_in[18];
    const float* decb   = (const float*)d_in[19];
    float* out = (float*)d_out;

    float *xa, *xb, *gates, *hbuf, *cbuf;
    cudaGetSymbolAddress((void**)&xa, g_xa);
    cudaGetSymbolAddress((void**)&xb, g_xb);
    cudaGetSymbolAddress((void**)&gates, g_gates);
    cudaGetSymbolAddress((void**)&hbuf, g_h);
    cudaGetSymbolAddress((void**)&cbuf, g_c);

    const size_t stateN = (size_t)BB * NHID;              // 65536
    const size_t decN   = (size_t)TT * BB * NTOK;         // 131072000

    // 1) embedding -> xa
    embed_kernel<<<TT * BB, 256>>>(tokens, embW, xa);

    float* xin = xa;
    float* xo  = xb;
    for (int l = 0; l < NLAYERS; l++) {
        // 2a) gate pre-activations for ALL timesteps (tf32-split tensor cores)
        mma_gemm_abt_tf32<<<dim3((TT * BB) / 128, G4 / 128), 256>>>(
            xin, Wih + (size_t)l * G4 * NHID, gates,
            TT * BB, G4, NHID, bih + (size_t)l * G4, bhh + (size_t)l * G4);

        cudaMemcpyAsync(hbuf, h0 + (size_t)l * stateN, stateN * sizeof(float),
                        cudaMemcpyDeviceToDevice, 0);
        cudaMemcpyAsync(cbuf, c0 + (size_t)l * stateN, stateN * sizeof(float),
                        cudaMemcpyDeviceToDevice, 0);

        // 2b) recurrence
        for (int t = 0; t < TT; t++) {
            float* gt = gates + (size_t)t * BB * G4;
            hh_gemm_kernel<<<dim3(128, NB), 256>>>(
                hbuf, Whh + (size_t)l * NB * 1024 * BS, gt);
            lstm_mha_kernel<<<BB, 1024>>>(
                gt, hbuf, cbuf, wq, bq, wk, bk, wv, bv, wfc, bfc, lng, lnb,
                xo + (size_t)t * BB * NHID);
        }

        // 2c) final states into output tail
        cudaMemcpyAsync(out + decN + (size_t)l * stateN, hbuf,
                        stateN * sizeof(float), cudaMemcpyDeviceToDevice, 0);
        cudaMemcpyAsync(out + decN + 2 * stateN + (size_t)l * stateN, cbuf,
                        stateN * sizeof(float), cudaMemcpyDeviceToDevice, 0);

        float* tmp = xin; xin = xo; xo = tmp;
    }

    // 3) decoder: out[t,b,:] = x @ decW^T + decb   (bf16-split tensor cores)
    mma_gemm_abt<<<dim3((TT * BB) / 128, NTOK / 128), 256>>>(
        xin, decW, out, TT * BB, NTOK, NHID, decb, nullptr);
}

// round 8
// speedup vs baseline: 1.4355x; 1.0026x over previous
#include <cuda_runtime.h>
#include <cuda_bf16.h>
#include <cstdint>
#include <cstddef>

// Problem constants
#define TT 64
#define BB 64
#define NHID 1024
#define NB 4
#define BS 256
#define G4 4096            // NB * 4*BS gate width per (t,b)
#define NTOK 32000
#define DKq 16
#define NLAYERS 2

// ---------------- scratch (static __device__ arrays; no allocations) -------
__device__ float g_xa[(size_t)TT * BB * NHID];     // 16 MB
__device__ float g_xb[(size_t)TT * BB * NHID];     // 16 MB
__device__ float g_gates[(size_t)TT * BB * G4];    // 64 MB
__device__ float g_h[BB * NHID];
__device__ float g_c[BB * NHID];

__device__ __forceinline__ float sigf(float x) { return 1.f / (1.f + expf(-x)); }

// ---------------- embedding gather ----------------
__global__ void embed_kernel(const int* __restrict__ tokens,
                             const float* __restrict__ embW,
                             float* __restrict__ x) {
    int row = blockIdx.x;                       // t*B + b
    int tok = tokens[row];
    const float4* src = (const float4*)&embW[(size_t)tok * NHID];
    float4* dst = (float4*)&x[(size_t)row * NHID];
    dst[threadIdx.x] = src[threadIdx.x];
}

// ===================== common MMA helpers =====================
#define LDSM4(R, ptr) do {                                                   \
    uint32_t _a = (uint32_t)__cvta_generic_to_shared(ptr);                   \
    asm volatile("ldmatrix.sync.aligned.m8n8.x4.shared.b16 {%0,%1,%2,%3},[%4];" \
        : "=r"((R)[0]), "=r"((R)[1]), "=r"((R)[2]), "=r"((R)[3]) : "r"(_a)); \
} while (0)

#define MMA16816(c, a, b0v, b1v) asm volatile(                               \
    "mma.sync.aligned.m16n8k16.row.col.f32.bf16.bf16.f32 "                   \
    "{%0,%1,%2,%3},{%4,%5,%6,%7},{%8,%9},{%0,%1,%2,%3};\n"                   \
    : "+f"((c)[0]), "+f"((c)[1]), "+f"((c)[2]), "+f"((c)[3])                 \
    : "r"((a)[0]), "r"((a)[1]), "r"((a)[2]), "r"((a)[3]),                    \
      "r"(b0v), "r"(b1v))

#define MMATF32(c, a, b0v, b1v) asm volatile(                                \
    "mma.sync.aligned.m16n8k8.row.col.f32.tf32.tf32.f32 "                    \
    "{%0,%1,%2,%3},{%4,%5,%6,%7},{%8,%9},{%0,%1,%2,%3};\n"                   \
    : "+f"((c)[0]), "+f"((c)[1]), "+f"((c)[2]), "+f"((c)[3])                 \
    : "r"((a)[0]), "r"((a)[1]), "r"((a)[2]), "r"((a)[3]),                    \
      "r"(b0v), "r"(b1v))

__device__ __forceinline__ uint32_t f2tf32(float x) {
    uint32_t r;
    asm("cvt.rna.tf32.f32 %0, %1;" : "=r"(r) : "f"(x));
    return r;
}
__device__ __forceinline__ float tf32f(uint32_t r) {
    return __uint_as_float(r);
}

// ============ bf16-split tensor-core GEMM (decoder): C = A·Bᵀ (+bias) ======
// Block tile 128x128x32, 256 threads = 8 warps, warp tile 32x64.
__global__ __launch_bounds__(256, 1)
void mma_gemm_abt(const float* __restrict__ A, const float* __restrict__ B,
                  float* __restrict__ C, int M, int N, int K,
                  const float* __restrict__ bias1, const float* __restrict__ bias2) {
    __shared__ alignas(16) __nv_bfloat16 Ahi[128][40];
    __shared__ alignas(16) __nv_bfloat16 Alo[128][40];
    __shared__ alignas(16) __nv_bfloat16 Bhi[128][40];
    __shared__ alignas(16) __nv_bfloat16 Blo[128][40];

    const int tid  = threadIdx.x;
    const int warp = tid >> 5, lane = tid & 31;
    const int wm = warp >> 1, wn = warp & 1;
    const int m0 = blockIdx.x * 128;                // x = M tiles (fast) for B L2 reuse
    const int n0 = blockIdx.y * 128;

    float c_[2][8][4];
#pragma unroll
    for (int i = 0; i < 2; i++)
#pragma unroll
        for (int j = 0; j < 8; j++)
#pragma unroll
            for (int k = 0; k < 4; k++) c_[i][j][k] = 0.f;

    float4 pa[4], pb[4];
    int prow[4], pcol[4];
#pragma unroll
    for (int f = 0; f < 4; f++) {
        int id = f * 256 + tid;
        prow[f] = id >> 3;
        pcol[f] = (id & 7) * 4;
    }

    const int nk = K >> 5;
#pragma unroll
    for (int f = 0; f < 4; f++) {
        pa[f] = *(const float4*)&A[(size_t)(m0 + prow[f]) * K + pcol[f]];
        pb[f] = *(const float4*)&B[(size_t)(n0 + prow[f]) * K + pcol[f]];
    }

    for (int kc = 0; kc < nk; kc++) {
        __syncthreads();
#pragma unroll
        for (int f = 0; f < 4; f++) {
            int r = prow[f], cc = pcol[f];
            float4 va = pa[f], vb = pb[f];
            __nv_bfloat16 ax = __float2bfloat16(va.x), ay = __float2bfloat16(va.y);
            __nv_bfloat16 az = __float2bfloat16(va.z), aw = __float2bfloat16(va.w);
            __nv_bfloat16 lx = __float2bfloat16(va.x - __bfloat162float(ax));
            __nv_bfloat16 ly = __float2bfloat16(va.y - __bfloat162float(ay));
            __nv_bfloat16 lz = __float2bfloat16(va.z - __bfloat162float(az));
            __nv_bfloat16 lw = __float2bfloat16(va.w - __bfloat162float(aw));
            __nv_bfloat162 t;
            t.x = ax; t.y = ay; *(__nv_bfloat162*)&Ahi[r][cc + 0] = t;
            t.x = az; t.y = aw; *(__nv_bfloat162*)&Ahi[r][cc + 2] = t;
            t.x = lx; t.y = ly; *(__nv_bfloat162*)&Alo[r][cc + 0] = t;
            t.x = lz; t.y = lw; *(__nv_bfloat162*)&Alo[r][cc + 2] = t;

            __nv_bfloat16 bx = __float2bfloat16(vb.x), by = __float2bfloat16(vb.y);
            __nv_bfloat16 bz = __float2bfloat16(vb.z), bw = __float2bfloat16(vb.w);
            __nv_bfloat16 mx = __float2bfloat16(vb.x - __bfloat162float(bx));
            __nv_bfloat16 my = __float2bfloat16(vb.y - __bfloat162float(by));
            __nv_bfloat16 mz = __float2bfloat16(vb.z - __bfloat162float(bz));
            __nv_bfloat16 mw = __float2bfloat16(vb.w - __bfloat162float(bw));
            t.x = bx; t.y = by; *(__nv_bfloat162*)&Bhi[r][cc + 0] = t;
            t.x = bz; t.y = bw; *(__nv_bfloat162*)&Bhi[r][cc + 2] = t;
            t.x = mx; t.y = my; *(__nv_bfloat162*)&Blo[r][cc + 0] = t;
            t.x = mz; t.y = mw; *(__nv_bfloat162*)&Blo[r][cc + 2] = t;
        }
        __syncthreads();

        if (kc + 1 < nk) {
            int kb = (kc + 1) << 5;
#pragma unroll
            for (int f = 0; f < 4; f++) {
                pa[f] = *(const float4*)&A[(size_t)(m0 + prow[f]) * K + kb + pcol[f]];
                pb[f] = *(const float4*)&B[(size_t)(n0 + prow[f]) * K + kb + pcol[f]];
            }
        }

#pragma unroll
        for (int ks = 0; ks < 2; ks++) {
            const int kb = ks * 16;
            uint32_t ah[2][4], al[2][4], bh[4][4], bl[4][4];
#pragma unroll
            for (int mt = 0; mt < 2; mt++) {
                int row = wm * 32 + mt * 16 + (lane & 15);
                int ko  = kb + ((lane >> 4) << 3);
                LDSM4(ah[mt], &Ahi[row][ko]);
                LDSM4(al[mt], &Alo[row][ko]);
            }
#pragma unroll
            for (int p = 0; p < 4; p++) {
                int row = wn * 64 + p * 16 + ((lane >> 4) << 3) + (lane & 7);
                int ko  = kb + (((lane >> 3) & 1) << 3);
                LDSM4(bh[p], &Bhi[row][ko]);
                LDSM4(bl[p], &Blo[row][ko]);
            }
#pragma unroll
            for (int mt = 0; mt < 2; mt++)
#pragma unroll
                for (int nt = 0; nt < 8; nt++) {
                    int p = nt >> 1, o = (nt & 1) * 2;
                    MMA16816(c_[mt][nt], ah[mt], bh[p][o], bh[p][o + 1]);
                    MMA16816(c_[mt][nt], ah[mt], bl[p][o], bl[p][o + 1]);
                    MMA16816(c_[mt][nt], al[mt], bh[p][o], bh[p][o + 1]);
                }
        }
    }

    const int g = lane >> 2, t2 = (lane & 3) * 2;
#pragma unroll
    for (int mt = 0; mt < 2; mt++) {
#pragma unroll
        for (int nt = 0; nt < 8; nt++) {
            int row = m0 + wm * 32 + mt * 16 + g;
            int col = n0 + wn * 64 + nt * 8 + t2;
            float b0a = 0.f, b1a = 0.f;
            if (bias1) { b0a += bias1[col]; b1a += bias1[col + 1]; }
            if (bias2) { b0a += bias2[col]; b1a += bias2[col + 1]; }
            float2 v0 = make_float2(c_[mt][nt][0] + b0a, c_[mt][nt][1] + b1a);
            float2 v1 = make_float2(c_[mt][nt][2] + b0a, c_[mt][nt][3] + b1a);
            *(float2*)&C[(size_t)row * N + col]       = v0;
            *(float2*)&C[(size_t)(row + 8) * N + col] = v1;
        }
    }
}

// ============ tf32-split tensor-core GEMM (ih gates): C = A·Bᵀ (+bias) =====
// Per-product error ~2^-21 — safe inside the recurrence.
// Block tile 128x128x16, 256 threads = 8 warps, warp tile 32x64.
__global__ __launch_bounds__(256)
void mma_gemm_abt_tf32(const float* __restrict__ A, const float* __restrict__ B,
                       float* __restrict__ C, int M, int N, int K,
                       const float* __restrict__ bias1, const float* __restrict__ bias2) {
    __shared__ alignas(16) uint32_t Ahi[128][20];
    __shared__ alignas(16) uint32_t Alo[128][20];
    __shared__ alignas(16) uint32_t Bhi[128][20];
    __shared__ alignas(16) uint32_t Blo[128][20];

    const int tid  = threadIdx.x;
    const int warp = tid >> 5, lane = tid & 31;
    const int wm = warp >> 1, wn = warp & 1;
    const int gq = lane >> 2, t4 = lane & 3;
    const int m0 = blockIdx.x * 128;
    const int n0 = blockIdx.y * 128;

    float c_[2][8][4];
#pragma unroll
    for (int i = 0; i < 2; i++)
#pragma unroll
        for (int j = 0; j < 8; j++)
#pragma unroll
            for (int k = 0; k < 4; k++) c_[i][j][k] = 0.f;

    // tile 128x16 fp32 per operand = 512 float4; 2 per thread
    float4 pa[2], pb[2];
    int prow[2], pcol[2];
#pragma unroll
    for (int f = 0; f < 2; f++) {
        int id = f * 256 + tid;
        prow[f] = id >> 2;
        pcol[f] = (id & 3) * 4;
    }

    const int nk = K >> 4;
#pragma unroll
    for (int f = 0; f < 2; f++) {
        pa[f] = *(const float4*)&A[(size_t)(m0 + prow[f]) * K + pcol[f]];
        pb[f] = *(const float4*)&B[(size_t)(n0 + prow[f]) * K + pcol[f]];
    }

    for (int kc = 0; kc < nk; kc++) {
        __syncthreads();
#pragma unroll
        for (int f = 0; f < 2; f++) {
            int r = prow[f], cc = pcol[f];
            float4 va = pa[f], vb = pb[f];
            uint32_t h0 = f2tf32(va.x), h1 = f2tf32(va.y);
            uint32_t h2 = f2tf32(va.z), h3 = f2tf32(va.w);
            uint4 hv = make_uint4(h0, h1, h2, h3);
            uint4 lv = make_uint4(f2tf32(va.x - tf32f(h0)), f2tf32(va.y - tf32f(h1)),
                                  f2tf32(va.z - tf32f(h2)), f2tf32(va.w - tf32f(h3)));
            *(uint4*)&Ahi[r][cc] = hv;
            *(uint4*)&Alo[r][cc] = lv;

            h0 = f2tf32(vb.x); h1 = f2tf32(vb.y);
            h2 = f2tf32(vb.z); h3 = f2tf32(vb.w);
            hv = make_uint4(h0, h1, h2, h3);
            lv = make_uint4(f2tf32(vb.x - tf32f(h0)), f2tf32(vb.y - tf32f(h1)),
                            f2tf32(vb.z - tf32f(h2)), f2tf32(vb.w - tf32f(h3)));
            *(uint4*)&Bhi[r][cc] = hv;
            *(uint4*)&Blo[r][cc] = lv;
        }
        __syncthreads();

        if (kc + 1 < nk) {
            int kb = (kc + 1) << 4;
#pragma unroll
            for (int f = 0; f < 2; f++) {
                pa[f] = *(const float4*)&A[(size_t)(m0 + prow[f]) * K + kb + pcol[f]];
                pb[f] = *(const float4*)&B[(size_t)(n0 + prow[f]) * K + kb + pcol[f]];
            }
        }

#pragma unroll
        for (int ks = 0; ks < 2; ks++) {
            const int kb = ks * 8;
            uint32_t ah[2][4], al[2][4], bh[8][2], bl[8][2];
#pragma unroll
            for (int mt = 0; mt < 2; mt++) {
                int rb = wm * 32 + mt * 16;
                ah[mt][0] = Ahi[rb + gq][kb + t4];
                ah[mt][1] = Ahi[rb + 8 + gq][kb + t4];
                ah[mt][2] = Ahi[rb + gq][kb + t4 + 4];
                ah[mt][3] = Ahi[rb + 8 + gq][kb + t4 + 4];
                al[mt][0] = Alo[rb + gq][kb + t4];
                al[mt][1] = Alo[rb + 8 + gq][kb + t4];
                al[mt][2] = Alo[rb + gq][kb + t4 + 4];
                al[mt][3] = Alo[rb + 8 + gq][kb + t4 + 4];
            }
#pragma unroll
            for (int nt = 0; nt < 8; nt++) {
                int bn = wn * 64 + nt * 8 + gq;
                bh[nt][0] = Bhi[bn][kb + t4];
                bh[nt][1] = Bhi[bn][kb + t4 + 4];
                bl[nt][0] = Blo[bn][kb + t4];
                bl[nt][1] = Blo[bn][kb + t4 + 4];
            }
#pragma unroll
            for (int mt = 0; mt < 2; mt++)
#pragma unroll
                for (int nt = 0; nt < 8; nt++) {
                    MMATF32(c_[mt][nt], ah[mt], bh[nt][0], bh[nt][1]);
                    MMATF32(c_[mt][nt], ah[mt], bl[nt][0], bl[nt][1]);
                    MMATF32(c_[mt][nt], al[mt], bh[nt][0], bh[nt][1]);
                }
        }
    }

    const int t2 = t4 * 2;
#pragma unroll
    for (int mt = 0; mt < 2; mt++) {
#pragma unroll
        for (int nt = 0; nt < 8; nt++) {
            int row = m0 + wm * 32 + mt * 16 + gq;
            int col = n0 + wn * 64 + nt * 8 + t2;
            float b0a = 0.f, b1a = 0.f;
            if (bias1) { b0a += bias1[col]; b1a += bias1[col + 1]; }
            if (bias2) { b0a += bias2[col]; b1a += bias2[col + 1]; }
            float2 v0 = make_float2(c_[mt][nt][0] + b0a, c_[mt][nt][1] + b1a);
            float2 v1 = make_float2(c_[mt][nt][2] + b0a, c_[mt][nt][3] + b1a);
            *(float2*)&C[(size_t)row * N + col]       = v0;
            *(float2*)&C[(size_t)(row + 8) * N + col] = v1;
        }
    }
}

// ---------------- per-timestep: gates_t[b, n*1024+g] += h[b,n,:] . Whh[n,g,:]
__global__ void hh_gemm_kernel(const float* __restrict__ h,
                               const float* __restrict__ Whh,
                               float* __restrict__ gates_t) {
    __shared__ float hs[64 * 64];               // [kk][b]
    const int n = blockIdx.y;
    const int warp = threadIdx.x >> 5;
    const int lane = threadIdx.x & 31;
    const int g = blockIdx.x * 8 + warp;        // 0..1023
    const float* wrow = Whh + (size_t)(n * 1024 + g) * BS;

    float acc0 = 0.f, acc1 = 0.f;
    for (int kc = 0; kc < BS; kc += 64) {
        __syncthreads();
#pragma unroll
        for (int i = 0; i < 4; i++) {
            int e = threadIdx.x + i * 256;
            int b = e >> 4;
            int kk4 = (e & 15) << 2;
            float4 v = *(const float4*)&h[(size_t)b * NHID + n * BS + kc + kk4];
            hs[(kk4 + 0) * 64 + b] = v.x;
            hs[(kk4 + 1) * 64 + b] = v.y;
            hs[(kk4 + 2) * 64 + b] = v.z;
            hs[(kk4 + 3) * 64 + b] = v.w;
        }
        __syncthreads();
        const float4* wp = (const float4*)(wrow + kc);
#pragma unroll
        for (int k4 = 0; k4 < 16; k4++) {
            float4 w = wp[k4];
            int kk = k4 * 4;
            acc0 += w.x * hs[(kk + 0) * 64 + lane];
            acc0 += w.y * hs[(kk + 1) * 64 + lane];
            acc0 += w.z * hs[(kk + 2) * 64 + lane];
            acc0 += w.w * hs[(kk + 3) * 64 + lane];
            acc1 += w.x * hs[(kk + 0) * 64 + lane + 32];
            acc1 += w.y * hs[(kk + 1) * 64 + lane + 32];
            acc1 += w.z * hs[(kk + 2) * 64 + lane + 32];
            acc1 += w.w * hs[(kk + 3) * 64 + lane + 32];
        }
    }
    gates_t[(size_t)lane * G4 + n * 1024 + g]        += acc0;
    gates_t[(size_t)(lane + 32) * G4 + n * 1024 + g] += acc1;
}

// ---------------- fused LSTM + block-MHA + LayerNorm (1024 threads) --------
__global__ __launch_bounds__(1024)
void lstm_mha_kernel(const float* __restrict__ gates_t,
                     float* __restrict__ h, float* __restrict__ c,
                     const float* __restrict__ wq, const float* __restrict__ bq,
                     const float* __restrict__ wk, const float* __restrict__ bk,
                     const float* __restrict__ wv, const float* __restrict__ bv,
                     const float* __restrict__ wfc, const float* __restrict__ bfc,
                     const float* __restrict__ lng, const float* __restrict__ lnb,
                     float* __restrict__ xout) {
    __shared__ float hl[NB][BS];
    __shared__ float qs[NB][DKq], ks_[NB][DKq], vs[NB][DKq];
    __shared__ float attn[NB][NB];
    __shared__ float av[NB][DKq];
    __shared__ float red[NB][8], red2[NB][8];

    const int b = blockIdx.x;
    const int tid = threadIdx.x;
    const int n = tid >> 8, ti = tid & 255;
    const int lane = tid & 31;

    // LSTM cell (one element per thread)
    const float* gb = gates_t + (size_t)b * G4 + n * 1024;
    float ig = gb[ti], fg = gb[256 + ti], gg = gb[512 + ti], og = gb[768 + ti];
    float co = c[(size_t)b * NHID + n * BS + ti];
    float cn = sigf(fg) * co + sigf(ig) * tanhf(gg);
    c[(size_t)b * NHID + n * BS + ti] = cn;
    float hv = sigf(og) * tanhf(cn);
    hl[n][ti] = hv;
    __syncthreads();

    // q/k/v projections: 768 threads, each quad does one (p, n, d) dot
    if (tid < 768) {
        int combo = tid >> 2, q = tid & 3;
        int p = combo / 64, r2 = combo % 64, nn = r2 >> 4, d = r2 & 15;
        const float* W = (p == 0 ? wq : (p == 1 ? wk : wv)) + (size_t)d * BS + q * 64;
        const float* H = hl[nn] + q * 64;
        const float4* W4 = (const float4*)W;
        const float4* H4 = (const float4*)H;
        float s = 0.f;
#pragma unroll
        for (int k4 = 0; k4 < 16; k4++) {
            float4 w = W4[k4], hh = H4[k4];
            s += w.x * hh.x + w.y * hh.y + w.z * hh.z + w.w * hh.w;
        }
        s += __shfl_down_sync(0xffffffffu, s, 2);
        s += __shfl_down_sync(0xffffffffu, s, 1);
        if (q == 0) {
            s += (p == 0 ? bq : (p == 1 ? bk : bv))[d];
            if (p == 0) qs[nn][d] = s;
            else if (p == 1) ks_[nn][d] = s;
            else vs[nn][d] = s;
        }
    }
    __syncthreads();

    if (tid < 16) {
        int nn = tid >> 2, m = tid & 3;
        float s = 0.f;
#pragma unroll
        for (int d = 0; d < DKq; d++) s += qs[nn][d] * ks_[m][d];
        attn[nn][m] = s * 0.25f;       // 1/sqrt(16)
    }
    __syncthreads();
    if (tid < 4) {
        float s0 = attn[tid][0], s1 = attn[tid][1];
        float s2 = attn[tid][2], s3 = attn[tid][3];
        float mx = fmaxf(fmaxf(s0, s1), fmaxf(s2, s3));
        float e0 = expf(s0 - mx), e1 = expf(s1 - mx);
        float e2 = expf(s2 - mx), e3 = expf(s3 - mx);
        float inv = 1.f / (e0 + e1 + e2 + e3);
        attn[tid][0] = e0 * inv; attn[tid][1] = e1 * inv;
        attn[tid][2] = e2 * inv; attn[tid][3] = e3 * inv;
    }
    __syncthreads();
    if (tid < 64) {
        int nn = tid >> 4, d = tid & 15;
        av[nn][d] = attn[nn][0] * vs[0][d] + attn[nn][1] * vs[1][d] +
                    attn[nn][2] * vs[2][d] + attn[nn][3] * vs[3][d];
    }
    __syncthreads();

    // out projection + residual
    float w[DKq];
    const float4* wr = (const float4*)&wfc[(size_t)ti * DKq];
#pragma unroll
    for (int q4 = 0; q4 < 4; q4++) {
        float4 v = wr[q4];
        w[q4 * 4 + 0] = v.x; w[q4 * 4 + 1] = v.y;
        w[q4 * 4 + 2] = v.z; w[q4 * 4 + 3] = v.w;
    }
    float o = bfc[ti];
#pragma unroll
    for (int d = 0; d < DKq; d++) o += av[n][d] * w[d];
    float v = o + hv;

    // LayerNorm over the 256-thread group of each n (all 4 in parallel)
    float s = v, s2 = v * v;
#pragma unroll
    for (int off = 16; off; off >>= 1) {
        s  += __shfl_down_sync(0xffffffffu, s, off);
        s2 += __shfl_down_sync(0xffffffffu, s2, off);
    }
    int gw = (tid >> 5) & 7;
    if (lane == 0) { red[n][gw] = s; red2[n][gw] = s2; }
    __syncthreads();
    if (ti == 0) {
        float S = 0.f, S2 = 0.f;
#pragma unroll
        for (int w2 = 0; w2 < 8; w2++) { S += red[n][w2]; S2 += red2[n][w2]; }
        red[n][0]  = S * (1.f / 256.f);
        red2[n][0] = S2 * (1.f / 256.f);
    }
    __syncthreads();
    float mu = red[n][0];
    float var = red2[n][0] - mu * mu;
    float y = (v - mu) * rsqrtf(var + 1e-5f) * lng[ti] + lnb[ti];
    h[(size_t)b * NHID + n * BS + ti] = y;
    xout[(size_t)b * NHID + n * BS + ti] = y;
}

// ---------------- host orchestration ----------------
extern "C" void kernel_launch(void* const* d_in, const int* in_sizes, int n_in,
                              void* d_out, int out_size) {
    (void)in_sizes; (void)n_in; (void)out_size;
    const int*   tokens = (const int*)d_in[0];
    const float* h0     = (const float*)d_in[1];
    const float* c0     = (const float*)d_in[2];
    const float* embW   = (const float*)d_in[3];
    const float* Wih    = (const float*)d_in[4];
    const float* Whh    = (const float*)d_in[5];
    const float* bih    = (const float*)d_in[6];
    const float* bhh    = (const float*)d_in[7];
    const float* wq     = (const float*)d_in[8];
    const float* bq     = (const float*)d_in[9];
    const float* wk     = (const float*)d_in[10];
    const float* bk     = (const float*)d_in[11];
    const float* wv     = (const float*)d_in[12];
    const float* bv     = (const float*)d_in[13];
    const float* wfc    = (const float*)d_in[14];
    const float* bfc    = (const float*)d_in[15];
    const float* lng    = (const float*)d_in[16];
    const float* lnb    = (const float*)d_in[17];
    const float* decW   = (const float*)d_in[18];
    const float* decb   = (const float*)d_in[19];
    float* out = (float*)d_out;

    float *xa, *xb, *gates, *hbuf, *cbuf;
    cudaGetSymbolAddress((void**)&xa, g_xa);
    cudaGetSymbolAddress((void**)&xb, g_xb);
    cudaGetSymbolAddress((void**)&gates, g_gates);
    cudaGetSymbolAddress((void**)&hbuf, g_h);
    cudaGetSymbolAddress((void**)&cbuf, g_c);

    const size_t stateN = (size_t)BB * NHID;              // 65536
    const size_t decN   = (size_t)TT * BB * NTOK;         // 131072000

    // 1) embedding -> xa
    embed_kernel<<<TT * BB, 256>>>(tokens, embW, xa);

    float* xin = xa;
    float* xo  = xb;
    for (int l = 0; l < NLAYERS; l++) {
        // 2a) gate pre-activations for ALL timesteps (tf32-split tensor cores)
        mma_gemm_abt_tf32<<<dim3((TT * BB) / 128, G4 / 128), 256>>>(
            xin, Wih + (size_t)l * G4 * NHID, gates,
            TT * BB, G4, NHID, bih + (size_t)l * G4, bhh + (size_t)l * G4);

        cudaMemcpyAsync(hbuf, h0 + (size_t)l * stateN, stateN * sizeof(float),
                        cudaMemcpyDeviceToDevice, 0);
        cudaMemcpyAsync(cbuf, c0 + (size_t)l * stateN, stateN * sizeof(float),
                        cudaMemcpyDeviceToDevice, 0);

        // 2b) recurrence
        for (int t = 0; t < TT; t++) {
            float* gt = gates + (size_t)t * BB * G4;
            hh_gemm_kernel<<<dim3(128, NB), 256>>>(
                hbuf, Whh + (size_t)l * NB * 1024 * BS, gt);
            lstm_mha_kernel<<<BB, 1024>>>(
                gt, hbuf, cbuf, wq, bq, wk, bk, wv, bv, wfc, bfc, lng, lnb,
                xo + (size_t)t * BB * NHID);
        }

        // 2c) final states into output tail
        cudaMemcpyAsync(out + decN + (size_t)l * stateN, hbuf,
                        stateN * sizeof(float), cudaMemcpyDeviceToDevice, 0);
        cudaMemcpyAsync(out + decN + 2 * stateN + (size_t)l * stateN, cbuf,
                        stateN * sizeof(float), cudaMemcpyDeviceToDevice, 0);

        float* tmp = xin; xin = xo; xo = tmp;
    }

    // 3) decoder: out[t,b,:] = x @ decW^T + decb   (bf16-split tensor cores)
    mma_gemm_abt<<<dim3((TT * BB) / 128, NTOK / 128), 256>>>(
        xin, decW, out, TT * BB, NTOK, NHID, decb, nullptr);
}

// round 12
// speedup vs baseline: 2.0897x; 1.4557x over previous
#include <cuda_runtime.h>
#include <cuda_bf16.h>
#include <cstdint>
#include <cstddef>

#define TT 64
#define BB 64
#define NHID 1024
#define NB 4
#define BS 256
#define G4 4096
#define NTOK 32000
#define DKq 16
#define NLAYERS 2

// ---------------- scratch (static __device__ arrays) ----------------------
__device__ float g_xa[(size_t)TT * BB * NHID];
__device__ float g_xb[(size_t)TT * BB * NHID];
__device__ float g_gates[(size_t)TT * BB * G4];
__device__ float g_h[BB * NHID];
__device__ float g_hh[(size_t)BB * G4];
__device__ unsigned g_bar_cnt = 0;
__device__ volatile unsigned g_bar_gen = 0;

__device__ __forceinline__ float sigf(float x) { return 1.f / (1.f + expf(-x)); }

// ---------------- embedding gather ----------------
__global__ void embed_kernel(const int* __restrict__ tokens,
                             const float* __restrict__ embW,
                             float* __restrict__ x) {
    int row = blockIdx.x;
    int tok = tokens[row];
    const float4* src = (const float4*)&embW[(size_t)tok * NHID];
    float4* dst = (float4*)&x[(size_t)row * NHID];
    dst[threadIdx.x] = src[threadIdx.x];
}

// ===================== MMA helpers =====================
#define LDSM4(R, ptr) do {                                                   \
    uint32_t _a = (uint32_t)__cvta_generic_to_shared(ptr);                   \
    asm volatile("ldmatrix.sync.aligned.m8n8.x4.shared.b16 {%0,%1,%2,%3},[%4];" \
        : "=r"((R)[0]), "=r"((R)[1]), "=r"((R)[2]), "=r"((R)[3]) : "r"(_a)); \
} while (0)

#define MMA16816(c, a, b0v, b1v) asm volatile(                               \
    "mma.sync.aligned.m16n8k16.row.col.f32.bf16.bf16.f32 "                   \
    "{%0,%1,%2,%3},{%4,%5,%6,%7},{%8,%9},{%0,%1,%2,%3};\n"                   \
    : "+f"((c)[0]), "+f"((c)[1]), "+f"((c)[2]), "+f"((c)[3])                 \
    : "r"((a)[0]), "r"((a)[1]), "r"((a)[2]), "r"((a)[3]),                    \
      "r"(b0v), "r"(b1v))

// ============ bf16 2-term split GEMM (decoder): C = A·Bᵀ (+bias) ===========
__global__ __launch_bounds__(256, 1)
void mma_gemm_abt(const float* __restrict__ A, const float* __restrict__ B,
                  float* __restrict__ C, int M, int N, int K,
                  const float* __restrict__ bias1) {
    __shared__ alignas(16) __nv_bfloat16 Ahi[128][40];
    __shared__ alignas(16) __nv_bfloat16 Alo[128][40];
    __shared__ alignas(16) __nv_bfloat16 Bhi[128][40];
    __shared__ alignas(16) __nv_bfloat16 Blo[128][40];

    const int tid  = threadIdx.x;
    const int warp = tid >> 5, lane = tid & 31;
    const int wm = warp >> 1, wn = warp & 1;
    const int m0 = blockIdx.x * 128;
    const int n0 = blockIdx.y * 128;

    float c_[2][8][4];
#pragma unroll
    for (int i = 0; i < 2; i++)
#pragma unroll
        for (int j = 0; j < 8; j++)
#pragma unroll
            for (int k = 0; k < 4; k++) c_[i][j][k] = 0.f;

    float4 pa[4], pb[4];
    int prow[4], pcol[4];
#pragma unroll
    for (int f = 0; f < 4; f++) {
        int id = f * 256 + tid;
        prow[f] = id >> 3;
        pcol[f] = (id & 7) * 4;
    }

    const int nk = K >> 5;
#pragma unroll
    for (int f = 0; f < 4; f++) {
        pa[f] = *(const float4*)&A[(size_t)(m0 + prow[f]) * K + pcol[f]];
        pb[f] = *(const float4*)&B[(size_t)(n0 + prow[f]) * K + pcol[f]];
    }

    for (int kc = 0; kc < nk; kc++) {
        __syncthreads();
#pragma unroll
        for (int f = 0; f < 4; f++) {
            int r = prow[f], cc = pcol[f];
            float4 va = pa[f], vb = pb[f];
            __nv_bfloat16 ax = __float2bfloat16(va.x), ay = __float2bfloat16(va.y);
            __nv_bfloat16 az = __float2bfloat16(va.z), aw = __float2bfloat16(va.w);
            __nv_bfloat162 t;
            t.x = ax; t.y = ay; *(__nv_bfloat162*)&Ahi[r][cc + 0] = t;
            t.x = az; t.y = aw; *(__nv_bfloat162*)&Ahi[r][cc + 2] = t;
            t.x = __float2bfloat16(va.x - __bfloat162float(ax));
            t.y = __float2bfloat16(va.y - __bfloat162float(ay));
            *(__nv_bfloat162*)&Alo[r][cc + 0] = t;
            t.x = __float2bfloat16(va.z - __bfloat162float(az));
            t.y = __float2bfloat16(va.w - __bfloat162float(aw));
            *(__nv_bfloat162*)&Alo[r][cc + 2] = t;

            __nv_bfloat16 bx = __float2bfloat16(vb.x), by = __float2bfloat16(vb.y);
            __nv_bfloat16 bz = __float2bfloat16(vb.z), bw = __float2bfloat16(vb.w);
            t.x = bx; t.y = by; *(__nv_bfloat162*)&Bhi[r][cc + 0] = t;
            t.x = bz; t.y = bw; *(__nv_bfloat162*)&Bhi[r][cc + 2] = t;
            t.x = __float2bfloat16(vb.x - __bfloat162float(bx));
            t.y = __float2bfloat16(vb.y - __bfloat162float(by));
            *(__nv_bfloat162*)&Blo[r][cc + 0] = t;
            t.x = __float2bfloat16(vb.z - __bfloat162float(bz));
            t.y = __float2bfloat16(vb.w - __bfloat162float(bw));
            *(__nv_bfloat162*)&Blo[r][cc + 2] = t;
        }
        __syncthreads();

        if (kc + 1 < nk) {
            int kb = (kc + 1) << 5;
#pragma unroll
            for (int f = 0; f < 4; f++) {
                pa[f] = *(const float4*)&A[(size_t)(m0 + prow[f]) * K + kb + pcol[f]];
                pb[f] = *(const float4*)&B[(size_t)(n0 + prow[f]) * K + kb + pcol[f]];
            }
        }

#pragma unroll
        for (int ks = 0; ks < 2; ks++) {
            const int kb = ks * 16;
            uint32_t ah[2][4], al[2][4], bh[4][4], bl[4][4];
#pragma unroll
            for (int mt = 0; mt < 2; mt++) {
                int row = wm * 32 + mt * 16 + (lane & 15);
                int ko  = kb + ((lane >> 4) << 3);
                LDSM4(ah[mt], &Ahi[row][ko]);
                LDSM4(al[mt], &Alo[row][ko]);
            }
#pragma unroll
            for (int p = 0; p < 4; p++) {
                int row = wn * 64 + p * 16 + ((lane >> 4) << 3) + (lane & 7);
                int ko  = kb + (((lane >> 3) & 1) << 3);
                LDSM4(bh[p], &Bhi[row][ko]);
                LDSM4(bl[p], &Blo[row][ko]);
            }
#pragma unroll
            for (int mt = 0; mt < 2; mt++)
#pragma unroll
                for (int nt = 0; nt < 8; nt++) {
                    int p = nt >> 1, o = (nt & 1) * 2;
                    MMA16816(c_[mt][nt], ah[mt], bh[p][o], bh[p][o + 1]);
                    MMA16816(c_[mt][nt], ah[mt], bl[p][o], bl[p][o + 1]);
                    MMA16816(c_[mt][nt], al[mt], bh[p][o], bh[p][o + 1]);
                }
        }
    }

    const int g = lane >> 2, t2 = (lane & 3) * 2;
#pragma unroll
    for (int mt = 0; mt < 2; mt++) {
#pragma unroll
        for (int nt = 0; nt < 8; nt++) {
            int row = m0 + wm * 32 + mt * 16 + g;
            int col = n0 + wn * 64 + nt * 8 + t2;
            float b0a = bias1 ? bias1[col] : 0.f;
            float b1a = bias1 ? bias1[col + 1] : 0.f;
            float2 v0 = make_float2(c_[mt][nt][0] + b0a, c_[mt][nt][1] + b1a);
            float2 v1 = make_float2(c_[mt][nt][2] + b0a, c_[mt][nt][3] + b1a);
            *(float2*)&C[(size_t)row * N + col]       = v0;
            *(float2*)&C[(size_t)(row + 8) * N + col] = v1;
        }
    }
}

// ============ bf16 3-term (6-pass) GEMM for ih gates: ~fp32 accurate =======
__global__ __launch_bounds__(256, 1)
void mma_gemm_ih(const float* __restrict__ A, const float* __restrict__ B,
                 float* __restrict__ C, int M, int N, int K,
                 const float* __restrict__ bias1, const float* __restrict__ bias2) {
    __shared__ alignas(16) __nv_bfloat16 A0s[128][24], A1s[128][24], A2s[128][24];
    __shared__ alignas(16) __nv_bfloat16 B0s[128][24], B1s[128][24], B2s[128][24];

    const int tid  = threadIdx.x;
    const int warp = tid >> 5, lane = tid & 31;
    const int wm = warp >> 1, wn = warp & 1;
    const int m0 = blockIdx.x * 128;
    const int n0 = blockIdx.y * 128;

    float c_[2][8][4];
#pragma unroll
    for (int i = 0; i < 2; i++)
#pragma unroll
        for (int j = 0; j < 8; j++)
#pragma unroll
            for (int k = 0; k < 4; k++) c_[i][j][k] = 0.f;

    float4 pa[2], pb[2];
    int prow[2], pcol[2];
#pragma unroll
    for (int f = 0; f < 2; f++) {
        int id = f * 256 + tid;
        prow[f] = id >> 2;
        pcol[f] = (id & 3) * 4;
    }

    const int nk = K >> 4;
#pragma unroll
    for (int f = 0; f < 2; f++) {
        pa[f] = *(const float4*)&A[(size_t)(m0 + prow[f]) * K + pcol[f]];
        pb[f] = *(const float4*)&B[(size_t)(n0 + prow[f]) * K + pcol[f]];
    }

    for (int kc = 0; kc < nk; kc++) {
        __syncthreads();
#pragma unroll
        for (int f = 0; f < 2; f++) {
            int r = prow[f], cc = pcol[f];
            float vv[4];
            float4 va = pa[f];
            vv[0] = va.x; vv[1] = va.y; vv[2] = va.z; vv[3] = va.w;
#pragma unroll
            for (int j = 0; j < 4; j += 2) {
                __nv_bfloat16 h0 = __float2bfloat16(vv[j]);
                __nv_bfloat16 h1 = __float2bfloat16(vv[j + 1]);
                float r0 = vv[j] - __bfloat162float(h0);
                float r1 = vv[j + 1] - __bfloat162float(h1);
                __nv_bfloat16 m0b = __float2bfloat16(r0);
                __nv_bfloat16 m1b = __float2bfloat16(r1);
                __nv_bfloat162 t;
                t.x = h0; t.y = h1; *(__nv_bfloat162*)&A0s[r][cc + j] = t;
                t.x = m0b; t.y = m1b; *(__nv_bfloat162*)&A1s[r][cc + j] = t;
                t.x = __float2bfloat16(r0 - __bfloat162float(m0b));
                t.y = __float2bfloat16(r1 - __bfloat162float(m1b));
                *(__nv_bfloat162*)&A2s[r][cc + j] = t;
            }
            float4 vb = pb[f];
            vv[0] = vb.x; vv[1] = vb.y; vv[2] = vb.z; vv[3] = vb.w;
#pragma unroll
            for (int j = 0; j < 4; j += 2) {
                __nv_bfloat16 h0 = __float2bfloat16(vv[j]);
                __nv_bfloat16 h1 = __float2bfloat16(vv[j + 1]);
                float r0 = vv[j] - __bfloat162float(h0);
                float r1 = vv[j + 1] - __bfloat162float(h1);
                __nv_bfloat16 m0b = __float2bfloat16(r0);
                __nv_bfloat16 m1b = __float2bfloat16(r1);
                __nv_bfloat162 t;
                t.x = h0; t.y = h1; *(__nv_bfloat162*)&B0s[r][cc + j] = t;
                t.x = m0b; t.y = m1b; *(__nv_bfloat162*)&B1s[r][cc + j] = t;
                t.x = __float2bfloat16(r0 - __bfloat162float(m0b));
                t.y = __float2bfloat16(r1 - __bfloat162float(m1b));
                *(__nv_bfloat162*)&B2s[r][cc + j] = t;
            }
        }
        __syncthreads();

        if (kc + 1 < nk) {
            int kb = (kc + 1) << 4;
#pragma unroll
            for (int f = 0; f < 2; f++) {
                pa[f] = *(const float4*)&A[(size_t)(m0 + prow[f]) * K + kb + pcol[f]];
                pb[f] = *(const float4*)&B[(size_t)(n0 + prow[f]) * K + kb + pcol[f]];
            }
        }

        uint32_t a0[2][4], a1[2][4], a2[2][4];
#pragma unroll
        for (int mt = 0; mt < 2; mt++) {
            int row = wm * 32 + mt * 16 + (lane & 15);
            int ko  = (lane >> 4) << 3;
            LDSM4(a0[mt], &A0s[row][ko]);
            LDSM4(a1[mt], &A1s[row][ko]);
            LDSM4(a2[mt], &A2s[row][ko]);
        }
#pragma unroll
        for (int p = 0; p < 4; p++) {
            uint32_t b0[4], b1[4], b2[4];
            int row = wn * 64 + p * 16 + ((lane >> 4) << 3) + (lane & 7);
            int ko  = ((lane >> 3) & 1) << 3;
            LDSM4(b0, &B0s[row][ko]);
            LDSM4(b1, &B1s[row][ko]);
            LDSM4(b2, &B2s[row][ko]);
#pragma unroll
            for (int mt = 0; mt < 2; mt++)
#pragma unroll
                for (int o2 = 0; o2 < 2; o2++) {
                    int nt = 2 * p + o2, o = o2 * 2;
                    MMA16816(c_[mt][nt], a0[mt], b0[o], b0[o + 1]);
                    MMA16816(c_[mt][nt], a0[mt], b1[o], b1[o + 1]);
                    MMA16816(c_[mt][nt], a1[mt], b0[o], b0[o + 1]);
                    MMA16816(c_[mt][nt], a0[mt], b2[o], b2[o + 1]);
                    MMA16816(c_[mt][nt], a1[mt], b1[o], b1[o + 1]);
                    MMA16816(c_[mt][nt], a2[mt], b0[o], b0[o + 1]);
                }
        }
    }

    const int g = lane >> 2, t2 = (lane & 3) * 2;
#pragma unroll
    for (int mt = 0; mt < 2; mt++) {
#pragma unroll
        for (int nt = 0; nt < 8; nt++) {
            int row = m0 + wm * 32 + mt * 16 + g;
            int col = n0 + wn * 64 + nt * 8 + t2;
            float b0a = bias1[col] + bias2[col];
            float b1a = bias1[col + 1] + bias2[col + 1];
            float2 v0 = make_float2(c_[mt][nt][0] + b0a, c_[mt][nt][1] + b1a);
            float2 v1 = make_float2(c_[mt][nt][2] + b0a, c_[mt][nt][3] + b1a);
            *(float2*)&C[(size_t)row * N + col]       = v0;
            *(float2*)&C[(size_t)(row + 8) * N + col] = v1;
        }
    }
}

// ============ persistent recurrence kernel (one launch per layer) ==========
// 128 CTAs x 512 threads, all co-resident. Phase A: hh GEMM (weights in smem
// for the whole layer). Phase B (CTAs 0..63): fused LSTM+MHA+LN, c in regs.
#define RK_CTAS 128
#define RSM_FLOATS (8192 + 16640 + 1024 + 64 + 64 + 64 + 16 + 64 + 32 + 32)
#define RSM_BYTES (RSM_FLOATS * 4)

__device__ __forceinline__ void grid_barrier() {
    __syncthreads();
    if (threadIdx.x == 0) {
        __threadfence();
        unsigned gen = g_bar_gen;
        if (atomicAdd(&g_bar_cnt, 1u) == RK_CTAS - 1) {
            g_bar_cnt = 0;
            __threadfence();
            g_bar_gen = gen + 1;
        } else {
            while (g_bar_gen == gen) __nanosleep(32);
        }
    }
    __syncthreads();
}

__global__ __launch_bounds__(512, 1)
void recur_kernel(const float* __restrict__ gates,   // [T][B][G4] ih preact
                  const float* __restrict__ Whh_l,   // [4096][256]
                  const float* __restrict__ h0_l,
                  const float* __restrict__ c0_l,
                  const float* __restrict__ wq, const float* __restrict__ bq,
                  const float* __restrict__ wk, const float* __restrict__ bk,
                  const float* __restrict__ wv, const float* __restrict__ bv,
                  const float* __restrict__ wfc, const float* __restrict__ bfc,
                  const float* __restrict__ lng, const float* __restrict__ lnb,
                  float* __restrict__ xout,          // [T][B][NHID]
                  float* __restrict__ cfin) {        // [B][NHID]
    extern __shared__ float sm[];
    float* ws   = sm;                 // 8192
    float* hs   = sm + 8192;          // 16640 (pitch 65, [k][b])
    float* gT   = hs;                 // alias (used after compute)
    float* hl   = sm + 24832;         // 1024
    float* qs   = sm + 25856;         // 64
    float* ks_  = sm + 25920;         // 64
    float* vs   = sm + 25984;         // 64
    float* attn = sm + 26048;         // 16
    float* av   = sm + 26064;         // 64
    float* red  = sm + 26128;         // 32
    float* red2 = sm + 26160;         // 32

    const int tid  = threadIdx.x;
    const int cta  = blockIdx.x;
    const int wid  = tid >> 5, lane = tid & 31;
    const int n    = cta >> 5;        // LSTM block owning this CTA's gate cols
    const int g0   = cta * 32;        // gate col base in [0,4096)
    const int b    = cta;             // phase-B batch (cta < 64)

    // W_hh slice (32 rows x 256) into smem once per layer
#pragma unroll
    for (int i = 0; i < 4; i++) {
        int id = i * 512 + tid;       // 2048 float4
        ((float4*)ws)[id] = ((const float4*)(Whh_l + (size_t)g0 * BS))[id];
    }

    // init g_h from h0 (128*512 = 65536 exactly)
    g_h[cta * 512 + tid] = h0_l[cta * 512 + tid];

    // c state in registers for phase-B CTAs
    float creg[2] = {0.f, 0.f};
    if (cta < 64) {
#pragma unroll
        for (int v = 0; v < 2; v++)
            creg[v] = c0_l[(size_t)b * NHID + v * 512 + tid];
    }
    grid_barrier();

    for (int t = 0; t < TT; t++) {
        // ---- phase A: stage h slice [64][256] -> hs[k][b] ----
#pragma unroll
        for (int i = 0; i < 8; i++) {
            int id = i * 512 + tid;   // 4096 float4
            int bb = id >> 6, k4 = id & 63;
            float4 v = __ldcg((const float4*)&g_h[(size_t)bb * NHID + n * BS] + k4);
            int k = k4 * 4;
            hs[(k + 0) * 65 + bb] = v.x;
            hs[(k + 1) * 65 + bb] = v.y;
            hs[(k + 2) * 65 + bb] = v.z;
            hs[(k + 3) * 65 + bb] = v.w;
        }
        __syncthreads();

        // ---- phase A compute: warp owns 2 gate cols, lanes = batches ----
        float a00 = 0.f, a01 = 0.f, a10 = 0.f, a11 = 0.f;
        {
            const float4* w0 = (const float4*)(ws + (size_t)(2 * wid) * BS);
            const float4* w1 = (const float4*)(ws + (size_t)(2 * wid + 1) * BS);
#pragma unroll 8
            for (int k4 = 0; k4 < 64; k4++) {
                float4 x0 = w0[k4], x1 = w1[k4];
                int k = k4 * 4;
                float h0v = hs[(k + 0) * 65 + lane];
                float h1v = hs[(k + 1) * 65 + lane];
                float h2v = hs[(k + 2) * 65 + lane];
                float h3v = hs[(k + 3) * 65 + lane];
                float p0v = hs[(k + 0) * 65 + lane + 32];
                float p1v = hs[(k + 1) * 65 + lane + 32];
                float p2v = hs[(k + 2) * 65 + lane + 32];
                float p3v = hs[(k + 3) * 65 + lane + 32];
                a00 = fmaf(x0.x, h0v, a00); a00 = fmaf(x0.y, h1v, a00);
                a00 = fmaf(x0.z, h2v, a00); a00 = fmaf(x0.w, h3v, a00);
                a01 = fmaf(x1.x, h0v, a01); a01 = fmaf(x1.y, h1v, a01);
                a01 = fmaf(x1.z, h2v, a01); a01 = fmaf(x1.w, h3v, a01);
                a10 = fmaf(x0.x, p0v, a10); a10 = fmaf(x0.y, p1v, a10);
                a10 = fmaf(x0.z, p2v, a10); a10 = fmaf(x0.w, p3v, a10);
                a11 = fmaf(x1.x, p0v, a11); a11 = fmaf(x1.y, p1v, a11);
                a11 = fmaf(x1.z, p2v, a11); a11 = fmaf(x1.w, p3v, a11);
            }
        }
        __syncthreads();
        gT[(2 * wid) * 65 + lane]          = a00;
        gT[(2 * wid + 1) * 65 + lane]      = a01;
        gT[(2 * wid) * 65 + lane + 32]     = a10;
        gT[(2 * wid + 1) * 65 + lane + 32] = a11;
        __syncthreads();
#pragma unroll
        for (int i = 0; i < 4; i++) {
            int id = i * 512 + tid;   // 2048
            int bb = id >> 5, gcol = id & 31;
            g_hh[(size_t)bb * G4 + g0 + gcol] = gT[gcol * 65 + bb];
        }
        grid_barrier();

        // ---- phase B: fused LSTM + MHA + LN on CTAs 0..63 ----
        if (cta < 64) {
            const float* gih = gates + ((size_t)t * BB + b) * G4;
            const float* ghh = g_hh + (size_t)b * G4;
            float hv[2];
#pragma unroll
            for (int v = 0; v < 2; v++) {
                int idx = v * 512 + tid, nn2 = idx >> 8, ti = idx & 255;
                int base = nn2 * 1024 + ti;
                float ig = __ldcg(gih + base)       + __ldcg(ghh + base);
                float fg = __ldcg(gih + base + 256) + __ldcg(ghh + base + 256);
                float gg = __ldcg(gih + base + 512) + __ldcg(ghh + base + 512);
                float og = __ldcg(gih + base + 768) + __ldcg(ghh + base + 768);
                float cn = sigf(fg) * creg[v] + sigf(ig) * tanhf(gg);
                creg[v] = cn;
                hv[v] = sigf(og) * tanhf(cn);
                hl[idx] = hv[v];
            }
            __syncthreads();

            // q/k/v: 192 dots, 4-thread quads (same math as before)
            for (int s = tid; s < 768; s += 512) {
                int combo = s >> 2, q = s & 3;
                int p = combo / 64, r2 = combo % 64, nn2 = r2 >> 4, d = r2 & 15;
                const float* W = (p == 0 ? wq : (p == 1 ? wk : wv)) + (size_t)d * BS + q * 64;
                const float* H = hl + nn2 * 256 + q * 64;
                const float4* W4 = (const float4*)W;
                const float4* H4 = (const float4*)H;
                float sv = 0.f;
#pragma unroll
                for (int k4 = 0; k4 < 16; k4++) {
                    float4 w = W4[k4], hh2 = H4[k4];
                    sv += w.x * hh2.x + w.y * hh2.y + w.z * hh2.z + w.w * hh2.w;
                }
                sv += __shfl_down_sync(0xffffffffu, sv, 2);
                sv += __shfl_down_sync(0xffffffffu, sv, 1);
                if (q == 0) {
                    sv += (p == 0 ? bq : (p == 1 ? bk : bv))[d];
                    if (p == 0) qs[nn2 * 16 + d] = sv;
                    else if (p == 1) ks_[nn2 * 16 + d] = sv;
                    else vs[nn2 * 16 + d] = sv;
                }
            }
            __syncthreads();

            if (tid < 16) {
                int nn2 = tid >> 2, m = tid & 3;
                float sv = 0.f;
#pragma unroll
                for (int d = 0; d < DKq; d++) sv += qs[nn2 * 16 + d] * ks_[m * 16 + d];
                attn[nn2 * 4 + m] = sv * 0.25f;
            }
            __syncthreads();
            if (tid < 4) {
                float s0 = attn[tid * 4 + 0], s1 = attn[tid * 4 + 1];
                float s2 = attn[tid * 4 + 2], s3 = attn[tid * 4 + 3];
                float mx = fmaxf(fmaxf(s0, s1), fmaxf(s2, s3));
                float e0 = expf(s0 - mx), e1 = expf(s1 - mx);
                float e2 = expf(s2 - mx), e3 = expf(s3 - mx);
                float inv = 1.f / (e0 + e1 + e2 + e3);
                attn[tid * 4 + 0] = e0 * inv; attn[tid * 4 + 1] = e1 * inv;
                attn[tid * 4 + 2] = e2 * inv; attn[tid * 4 + 3] = e3 * inv;
            }
            __syncthreads();
            if (tid < 64) {
                int nn2 = tid >> 4, d = tid & 15;
                av[nn2 * 16 + d] = attn[nn2 * 4 + 0] * vs[0 * 16 + d] +
                                   attn[nn2 * 4 + 1] * vs[1 * 16 + d] +
                                   attn[nn2 * 4 + 2] * vs[2 * 16 + d] +
                                   attn[nn2 * 4 + 3] * vs[3 * 16 + d];
            }
            __syncthreads();

            // out projection + residual + LN
            float val[2];
#pragma unroll
            for (int v = 0; v < 2; v++) {
                int idx = v * 512 + tid, nn2 = idx >> 8, ti = idx & 255;
                float w[DKq];
                const float4* wr = (const float4*)&wfc[(size_t)ti * DKq];
#pragma unroll
                for (int q4 = 0; q4 < 4; q4++) {
                    float4 vv = wr[q4];
                    w[q4 * 4 + 0] = vv.x; w[q4 * 4 + 1] = vv.y;
                    w[q4 * 4 + 2] = vv.z; w[q4 * 4 + 3] = vv.w;
                }
                float o = bfc[ti];
#pragma unroll
                for (int d = 0; d < DKq; d++) o += av[nn2 * 16 + d] * w[d];
                val[v] = o + hv[v];

                float s1 = val[v], sq = val[v] * val[v];
#pragma unroll
                for (int off = 16; off; off >>= 1) {
                    s1 += __shfl_down_sync(0xffffffffu, s1, off);
                    sq += __shfl_down_sync(0xffffffffu, sq, off);
                }
                if (lane == 0) {
                    int gw = (tid >> 5) & 7;
                    red[nn2 * 8 + gw]  = s1;
                    red2[nn2 * 8 + gw] = sq;
                }
            }
            __syncthreads();
            if (tid < 4) {
                float S = 0.f, S2 = 0.f;
#pragma unroll
                for (int w2 = 0; w2 < 8; w2++) {
                    S  += red[tid * 8 + w2];
                    S2 += red2[tid * 8 + w2];
                }
                red[tid * 8]  = S * (1.f / 256.f);
                red2[tid * 8] = S2 * (1.f / 256.f);
            }
            __syncthreads();
#pragma unroll
            for (int v = 0; v < 2; v++) {
                int idx = v * 512 + tid, nn2 = idx >> 8, ti = idx & 255;
                float mu = red[nn2 * 8];
                float var = red2[nn2 * 8] - mu * mu;
                float y = (val[v] - mu) * rsqrtf(var + 1e-5f) * lng[ti] + lnb[ti];
                g_h[(size_t)b * NHID + idx] = y;
                xout[((size_t)t * BB + b) * NHID + idx] = y;
            }
        }
        grid_barrier();
    }

    if (cta < 64) {
#pragma unroll
        for (int v = 0; v < 2; v++)
            cfin[(size_t)b * NHID + v * 512 + tid] = creg[v];
    }
}

// ---------------- host orchestration ----------------
extern "C" void kernel_launch(void* const* d_in, const int* in_sizes, int n_in,
                              void* d_out, int out_size) {
    (void)in_sizes; (void)n_in; (void)out_size;
    const int*   tokens = (const int*)d_in[0];
    const float* h0     = (const float*)d_in[1];
    const float* c0     = (const float*)d_in[2];
    const float* embW   = (const float*)d_in[3];
    const float* Wih    = (const float*)d_in[4];
    const float* Whh    = (const float*)d_in[5];
    const float* bih    = (const float*)d_in[6];
    const float* bhh    = (const float*)d_in[7];
    const float* wq     = (const float*)d_in[8];
    const float* bq     = (const float*)d_in[9];
    const float* wk     = (const float*)d_in[10];
    const float* bk     = (const float*)d_in[11];
    const float* wv     = (const float*)d_in[12];
    const float* bv     = (const float*)d_in[13];
    const float* wfc    = (const float*)d_in[14];
    const float* bfc    = (const float*)d_in[15];
    const float* lng    = (const float*)d_in[16];
    const float* lnb    = (const float*)d_in[17];
    const float* decW   = (const float*)d_in[18];
    const float* decb   = (const float*)d_in[19];
    float* out = (float*)d_out;

    float *xa, *xb, *gates, *hsym;
    cudaGetSymbolAddress((void**)&xa, g_xa);
    cudaGetSymbolAddress((void**)&xb, g_xb);
    cudaGetSymbolAddress((void**)&gates, g_gates);
    cudaGetSymbolAddress((void**)&hsym, g_h);

    cudaFuncSetAttribute(recur_kernel,
                         cudaFuncAttributeMaxDynamicSharedMemorySize, RSM_BYTES);

    const size_t stateN = (size_t)BB * NHID;              // 65536
    const size_t decN   = (size_t)TT * BB * NTOK;

    embed_kernel<<<TT * BB, 256>>>(tokens, embW, xa);

    float* xin = xa;
    float* xo  = xb;
    for (int l = 0; l < NLAYERS; l++) {
        mma_gemm_ih<<<dim3((TT * BB) / 128, G4 / 128), 256>>>(
            xin, Wih + (size_t)l * G4 * NHID, gates,
            TT * BB, G4, NHID, bih + (size_t)l * G4, bhh + (size_t)l * G4);

        recur_kernel<<<RK_CTAS, 512, RSM_BYTES>>>(
            gates, Whh + (size_t)l * G4 * BS,
            h0 + (size_t)l * stateN, c0 + (size_t)l * stateN,
            wq, bq, wk, bk, wv, bv, wfc, bfc, lng, lnb,
            xo, out + decN + 2 * stateN + (size_t)l * stateN);

        cudaMemcpyAsync(out + decN + (size_t)l * stateN, hsym,
                        stateN * sizeof(float), cudaMemcpyDeviceToDevice, 0);

        float* tmp = xin; xin = xo; xo = tmp;
    }

    mma_gemm_abt<<<dim3((TT * BB) / 128, NTOK / 128), 256>>>(
        xin, decW, out, TT * BB, NTOK, NHID, decb);
}

// round 13
// speedup vs baseline: 2.1622x; 1.0347x over previous
#include <cuda_runtime.h>
#include <cuda_bf16.h>
#include <cstdint>
#include <cstddef>

#define TT 64
#define BB 64
#define NHID 1024
#define NB 4
#define BS 256
#define G4 4096
#define NTOK 32000
#define DKq 16
#define NLAYERS 2

// ---------------- scratch (static __device__ arrays) ----------------------
__device__ float g_xa[(size_t)TT * BB * NHID];
__device__ float g_xb[(size_t)TT * BB * NHID];
__device__ float g_gates[(size_t)TT * BB * G4];
__device__ float g_h[BB * NHID];
__device__ float g_hh[(size_t)BB * G4];
// pre-split operand buffers
__device__ __nv_bfloat16 g_a0[(size_t)TT * BB * NHID];
__device__ __nv_bfloat16 g_a1[(size_t)TT * BB * NHID];
__device__ __nv_bfloat16 g_a2[(size_t)TT * BB * NHID];
__device__ __nv_bfloat16 g_w0[(size_t)G4 * NHID];
__device__ __nv_bfloat16 g_w1[(size_t)G4 * NHID];
__device__ __nv_bfloat16 g_w2[(size_t)G4 * NHID];
__device__ __nv_bfloat16 g_dh[(size_t)NTOK * NHID];
__device__ __nv_bfloat16 g_dl[(size_t)NTOK * NHID];

__device__ unsigned g_bar_cnt = 0;
__device__ volatile unsigned g_bar_gen = 0;

__device__ __forceinline__ float sigf(float x) { return 1.f / (1.f + expf(-x)); }

// ---------------- embedding gather ----------------
__global__ void embed_kernel(const int* __restrict__ tokens,
                             const float* __restrict__ embW,
                             float* __restrict__ x) {
    int row = blockIdx.x;
    int tok = tokens[row];
    const float4* src = (const float4*)&embW[(size_t)tok * NHID];
    float4* dst = (float4*)&x[(size_t)row * NHID];
    dst[threadIdx.x] = src[threadIdx.x];
}

// ---------------- bf16 split kernels (bit-exact vs in-GEMM splits) --------
__global__ void split2_kernel(const float* __restrict__ W,
                              __nv_bfloat16* __restrict__ hi,
                              __nv_bfloat16* __restrict__ lo, int n4) {
    int i = blockIdx.x * blockDim.x + threadIdx.x;
    for (; i < n4; i += gridDim.x * blockDim.x) {
        float4 v = ((const float4*)W)[i];
        __nv_bfloat16 h0 = __float2bfloat16(v.x), h1 = __float2bfloat16(v.y);
        __nv_bfloat16 h2 = __float2bfloat16(v.z), h3 = __float2bfloat16(v.w);
        __nv_bfloat162 a, b;
        a.x = h0; a.y = h1; b.x = h2; b.y = h3;
        ((__nv_bfloat162*)hi)[i * 2]     = a;
        ((__nv_bfloat162*)hi)[i * 2 + 1] = b;
        a.x = __float2bfloat16(v.x - __bfloat162float(h0));
        a.y = __float2bfloat16(v.y - __bfloat162float(h1));
        b.x = __float2bfloat16(v.z - __bfloat162float(h2));
        b.y = __float2bfloat16(v.w - __bfloat162float(h3));
        ((__nv_bfloat162*)lo)[i * 2]     = a;
        ((__nv_bfloat162*)lo)[i * 2 + 1] = b;
    }
}

__global__ void split3_kernel(const float* __restrict__ W,
                              __nv_bfloat16* __restrict__ t0,
                              __nv_bfloat16* __restrict__ t1,
                              __nv_bfloat16* __restrict__ t2, int n4) {
    int i = blockIdx.x * blockDim.x + threadIdx.x;
    for (; i < n4; i += gridDim.x * blockDim.x) {
        float4 v = ((const float4*)W)[i];
        float vv[4] = {v.x, v.y, v.z, v.w};
        __nv_bfloat16 h[4], m[4], l[4];
#pragma unroll
        for (int j = 0; j < 4; j++) {
            h[j] = __float2bfloat16(vv[j]);
            float r = vv[j] - __bfloat162float(h[j]);
            m[j] = __float2bfloat16(r);
            l[j] = __float2bfloat16(r - __bfloat162float(m[j]));
        }
        __nv_bfloat162 p;
        p.x = h[0]; p.y = h[1]; ((__nv_bfloat162*)t0)[i * 2]     = p;
        p.x = h[2]; p.y = h[3]; ((__nv_bfloat162*)t0)[i * 2 + 1] = p;
        p.x = m[0]; p.y = m[1]; ((__nv_bfloat162*)t1)[i * 2]     = p;
        p.x = m[2]; p.y = m[3]; ((__nv_bfloat162*)t1)[i * 2 + 1] = p;
        p.x = l[0]; p.y = l[1]; ((__nv_bfloat162*)t2)[i * 2]     = p;
        p.x = l[2]; p.y = l[3]; ((__nv_bfloat162*)t2)[i * 2 + 1] = p;
    }
}

// ===================== MMA / cp.async helpers =====================
#define LDSM4(R, ptr) do {                                                   \
    uint32_t _a = (uint32_t)__cvta_generic_to_shared(ptr);                   \
    asm volatile("ldmatrix.sync.aligned.m8n8.x4.shared.b16 {%0,%1,%2,%3},[%4];" \
        : "=r"((R)[0]), "=r"((R)[1]), "=r"((R)[2]), "=r"((R)[3]) : "r"(_a)); \
} while (0)

#define MMA16816(c, a, b0v, b1v) asm volatile(                               \
    "mma.sync.aligned.m16n8k16.row.col.f32.bf16.bf16.f32 "                   \
    "{%0,%1,%2,%3},{%4,%5,%6,%7},{%8,%9},{%0,%1,%2,%3};\n"                   \
    : "+f"((c)[0]), "+f"((c)[1]), "+f"((c)[2]), "+f"((c)[3])                 \
    : "r"((a)[0]), "r"((a)[1]), "r"((a)[2]), "r"((a)[3]),                    \
      "r"(b0v), "r"(b1v))

#define CPA16(sptr, gptr) do {                                               \
    uint32_t _s = (uint32_t)__cvta_generic_to_shared(sptr);                  \
    asm volatile("cp.async.ca.shared.global [%0], [%1], 16;"                 \
        :: "r"(_s), "l"(gptr));                                              \
} while (0)
#define CPCOMMIT() asm volatile("cp.async.commit_group;")
#define CPWAIT1()  asm volatile("cp.async.wait_group 1;")
#define CPWAIT0()  asm volatile("cp.async.wait_group 0;")

// ============ decoder GEMM: pre-split bf16, cp.async 2-stage ===============
// C[M,N] = Ahi/lo[M,K] x (Bhi/lo[N,K])^T (+bias). Same MMA order as before.
#define DEC_ARR 5120               // 128*40 bf16 per array
#define DEC_SMEM_BF16 (4 * 2 * DEC_ARR)   // 4 arrays x 2 stages
#define DEC_SMEM_BYTES (DEC_SMEM_BF16 * 2)

__global__ __launch_bounds__(256, 1)
void mma_gemm_dec(const __nv_bfloat16* __restrict__ Ahi_g,
                  const __nv_bfloat16* __restrict__ Alo_g,
                  const __nv_bfloat16* __restrict__ Bhi_g,
                  const __nv_bfloat16* __restrict__ Blo_g,
                  float* __restrict__ C, int M, int N, int K,
                  const float* __restrict__ bias1) {
    extern __shared__ __nv_bfloat16 smx[];
    const int tid  = threadIdx.x;
    const int warp = tid >> 5, lane = tid & 31;
    const int wm = warp >> 1, wn = warp & 1;
    const int m0 = blockIdx.x * 128;
    const int n0 = blockIdx.y * 128;

    float c_[2][8][4];
#pragma unroll
    for (int i = 0; i < 2; i++)
#pragma unroll
        for (int j = 0; j < 8; j++)
#pragma unroll
            for (int k = 0; k < 4; k++) c_[i][j][k] = 0.f;

    const int nk = K >> 5;

    // stage s arrays: Ahi,Alo at s*2+{0,1}; Bhi,Blo at 4*DEC_ARR offset region
    auto issue = [&](int kc) {
        int s = kc & 1;
        int kb = kc << 5;
        __nv_bfloat16* sa0 = smx + (s * 2 + 0) * DEC_ARR;
        __nv_bfloat16* sa1 = smx + (s * 2 + 1) * DEC_ARR;
        __nv_bfloat16* sb0 = smx + 4 * DEC_ARR + (s * 2 + 0) * DEC_ARR;
        __nv_bfloat16* sb1 = smx + 4 * DEC_ARR + (s * 2 + 1) * DEC_ARR;
#pragma unroll
        for (int f = 0; f < 2; f++) {
            int id = f * 256 + tid;           // 0..511
            int row = id >> 2, kc8 = (id & 3) * 8;
            size_t ga = (size_t)(m0 + row) * K + kb + kc8;
            size_t gb = (size_t)(n0 + row) * K + kb + kc8;
            CPA16(&sa0[row * 40 + kc8], Ahi_g + ga);
            CPA16(&sa1[row * 40 + kc8], Alo_g + ga);
            CPA16(&sb0[row * 40 + kc8], Bhi_g + gb);
            CPA16(&sb1[row * 40 + kc8], Blo_g + gb);
        }
        CPCOMMIT();
    };

    issue(0);
    for (int kc = 0; kc < nk; kc++) {
        if (kc + 1 < nk) { issue(kc + 1); CPWAIT1(); }
        else             { CPWAIT0(); }
        __syncthreads();

        int s = kc & 1;
        __nv_bfloat16* Ahi = smx + (s * 2 + 0) * DEC_ARR;
        __nv_bfloat16* Alo = smx + (s * 2 + 1) * DEC_ARR;
        __nv_bfloat16* Bhi = smx + 4 * DEC_ARR + (s * 2 + 0) * DEC_ARR;
        __nv_bfloat16* Blo = smx + 4 * DEC_ARR + (s * 2 + 1) * DEC_ARR;

#pragma unroll
        for (int ks = 0; ks < 2; ks++) {
            const int kb = ks * 16;
            uint32_t ah[2][4], al[2][4], bh[4][4], bl[4][4];
#pragma unroll
            for (int mt = 0; mt < 2; mt++) {
                int row = wm * 32 + mt * 16 + (lane & 15);
                int ko  = kb + ((lane >> 4) << 3);
                LDSM4(ah[mt], &Ahi[row * 40 + ko]);
                LDSM4(al[mt], &Alo[row * 40 + ko]);
            }
#pragma unroll
            for (int p = 0; p < 4; p++) {
                int row = wn * 64 + p * 16 + ((lane >> 4) << 3) + (lane & 7);
                int ko  = kb + (((lane >> 3) & 1) << 3);
                LDSM4(bh[p], &Bhi[row * 40 + ko]);
                LDSM4(bl[p], &Blo[row * 40 + ko]);
            }
#pragma unroll
            for (int mt = 0; mt < 2; mt++)
#pragma unroll
                for (int nt = 0; nt < 8; nt++) {
                    int p = nt >> 1, o = (nt & 1) * 2;
                    MMA16816(c_[mt][nt], ah[mt], bh[p][o], bh[p][o + 1]);
                    MMA16816(c_[mt][nt], ah[mt], bl[p][o], bl[p][o + 1]);
                    MMA16816(c_[mt][nt], al[mt], bh[p][o], bh[p][o + 1]);
                }
        }
        __syncthreads();
    }

    const int g = lane >> 2, t2 = (lane & 3) * 2;
#pragma unroll
    for (int mt = 0; mt < 2; mt++) {
#pragma unroll
        for (int nt = 0; nt < 8; nt++) {
            int row = m0 + wm * 32 + mt * 16 + g;
            int col = n0 + wn * 64 + nt * 8 + t2;
            float b0a = bias1 ? bias1[col] : 0.f;
            float b1a = bias1 ? bias1[col + 1] : 0.f;
            float2 v0 = make_float2(c_[mt][nt][0] + b0a, c_[mt][nt][1] + b1a);
            float2 v1 = make_float2(c_[mt][nt][2] + b0a, c_[mt][nt][3] + b1a);
            *(float2*)&C[(size_t)row * N + col]       = v0;
            *(float2*)&C[(size_t)(row + 8) * N + col] = v1;
        }
    }
}

// ============ ih GEMM: pre-split 3-term bf16, cp.async 2-stage =============
// Identical MMA order to R12's mma_gemm_ih => bit-exact gates.
#define IH_ARR 3072                // 128*24 bf16 per array
#define IH_SMEM_BF16 (12 * IH_ARR) // 6 arrays x 2 stages
#define IH_SMEM_BYTES (IH_SMEM_BF16 * 2)

__global__ __launch_bounds__(256, 1)
void mma_gemm_ih(const __nv_bfloat16* __restrict__ A0g,
                 const __nv_bfloat16* __restrict__ A1g,
                 const __nv_bfloat16* __restrict__ A2g,
                 const __nv_bfloat16* __restrict__ B0g,
                 const __nv_bfloat16* __restrict__ B1g,
                 const __nv_bfloat16* __restrict__ B2g,
                 float* __restrict__ C, int M, int N, int K,
                 const float* __restrict__ bias1, const float* __restrict__ bias2) {
    extern __shared__ __nv_bfloat16 smx[];
    const int tid  = threadIdx.x;
    const int warp = tid >> 5, lane = tid & 31;
    const int wm = warp >> 1, wn = warp & 1;
    const int m0 = blockIdx.x * 128;
    const int n0 = blockIdx.y * 128;

    float c_[2][8][4];
#pragma unroll
    for (int i = 0; i < 2; i++)
#pragma unroll
        for (int j = 0; j < 8; j++)
#pragma unroll
            for (int k = 0; k < 4; k++) c_[i][j][k] = 0.f;

    const int nk = K >> 4;

    auto issue = [&](int kc) {
        int s = kc & 1;
        int kb = kc << 4;
        int id = tid;                          // 0..255
        int row = id >> 1, kc8 = (id & 1) * 8;
        size_t ga = (size_t)(m0 + row) * K + kb + kc8;
        size_t gb = (size_t)(n0 + row) * K + kb + kc8;
        int so = row * 24 + kc8;
        CPA16(smx + (s * 3 + 0) * IH_ARR + so, A0g + ga);
        CPA16(smx + (s * 3 + 1) * IH_ARR + so, A1g + ga);
        CPA16(smx + (s * 3 + 2) * IH_ARR + so, A2g + ga);
        CPA16(smx + 6 * IH_ARR + (s * 3 + 0) * IH_ARR + so, B0g + gb);
        CPA16(smx + 6 * IH_ARR + (s * 3 + 1) * IH_ARR + so, B1g + gb);
        CPA16(smx + 6 * IH_ARR + (s * 3 + 2) * IH_ARR + so, B2g + gb);
        CPCOMMIT();
    };

    issue(0);
    for (int kc = 0; kc < nk; kc++) {
        if (kc + 1 < nk) { issue(kc + 1); CPWAIT1(); }
        else             { CPWAIT0(); }
        __syncthreads();

        int s = kc & 1;
        __nv_bfloat16* A0s = smx + (s * 3 + 0) * IH_ARR;
        __nv_bfloat16* A1s = smx + (s * 3 + 1) * IH_ARR;
        __nv_bfloat16* A2s = smx + (s * 3 + 2) * IH_ARR;
        __nv_bfloat16* B0s = smx + 6 * IH_ARR + (s * 3 + 0) * IH_ARR;
        __nv_bfloat16* B1s = smx + 6 * IH_ARR + (s * 3 + 1) * IH_ARR;
        __nv_bfloat16* B2s = smx + 6 * IH_ARR + (s * 3 + 2) * IH_ARR;

        uint32_t a0[2][4], a1[2][4], a2[2][4];
#pragma unroll
        for (int mt = 0; mt < 2; mt++) {
            int row = wm * 32 + mt * 16 + (lane & 15);
            int ko  = (lane >> 4) << 3;
            LDSM4(a0[mt], &A0s[row * 24 + ko]);
            LDSM4(a1[mt], &A1s[row * 24 + ko]);
            LDSM4(a2[mt], &A2s[row * 24 + ko]);
        }
#pragma unroll
        for (int p = 0; p < 4; p++) {
            uint32_t b0[4], b1[4], b2[4];
            int row = wn * 64 + p * 16 + ((lane >> 4) << 3) + (lane & 7);
            int ko  = ((lane >> 3) & 1) << 3;
            LDSM4(b0, &B0s[row * 24 + ko]);
            LDSM4(b1, &B1s[row * 24 + ko]);
            LDSM4(b2, &B2s[row * 24 + ko]);
#pragma unroll
            for (int mt = 0; mt < 2; mt++)
#pragma unroll
                for (int o2 = 0; o2 < 2; o2++) {
                    int nt = 2 * p + o2, o = o2 * 2;
                    MMA16816(c_[mt][nt], a0[mt], b0[o], b0[o + 1]);
                    MMA16816(c_[mt][nt], a0[mt], b1[o], b1[o + 1]);
                    MMA16816(c_[mt][nt], a1[mt], b0[o], b0[o + 1]);
                    MMA16816(c_[mt][nt], a0[mt], b2[o], b2[o + 1]);
                    MMA16816(c_[mt][nt], a1[mt], b1[o], b1[o + 1]);
                    MMA16816(c_[mt][nt], a2[mt], b0[o], b0[o + 1]);
                }
        }
        __syncthreads();
    }

    const int g = lane >> 2, t2 = (lane & 3) * 2;
#pragma unroll
    for (int mt = 0; mt < 2; mt++) {
#pragma unroll
        for (int nt = 0; nt < 8; nt++) {
            int row = m0 + wm * 32 + mt * 16 + g;
            int col = n0 + wn * 64 + nt * 8 + t2;
            float b0a = bias1[col] + bias2[col];
            float b1a = bias1[col + 1] + bias2[col + 1];
            float2 v0 = make_float2(c_[mt][nt][0] + b0a, c_[mt][nt][1] + b1a);
            float2 v1 = make_float2(c_[mt][nt][2] + b0a, c_[mt][nt][3] + b1a);
            *(float2*)&C[(size_t)row * N + col]       = v0;
            *(float2*)&C[(size_t)(row + 8) * N + col] = v1;
        }
    }
}

// ============ persistent recurrence kernel (UNCHANGED from R12) ============
#define RK_CTAS 128
#define RSM_FLOATS (8192 + 16640 + 1024 + 64 + 64 + 64 + 16 + 64 + 32 + 32)
#define RSM_BYTES (RSM_FLOATS * 4)

__device__ __forceinline__ void grid_barrier() {
    __syncthreads();
    if (threadIdx.x == 0) {
        __threadfence();
        unsigned gen = g_bar_gen;
        if (atomicAdd(&g_bar_cnt, 1u) == RK_CTAS - 1) {
            g_bar_cnt = 0;
            __threadfence();
            g_bar_gen = gen + 1;
        } else {
            while (g_bar_gen == gen) __nanosleep(32);
        }
    }
    __syncthreads();
}

__global__ __launch_bounds__(512, 1)
void recur_kernel(const float* __restrict__ gates,
                  const float* __restrict__ Whh_l,
                  const float* __restrict__ h0_l,
                  const float* __restrict__ c0_l,
                  const float* __restrict__ wq, const float* __restrict__ bq,
                  const float* __restrict__ wk, const float* __restrict__ bk,
                  const float* __restrict__ wv, const float* __restrict__ bv,
                  const float* __restrict__ wfc, const float* __restrict__ bfc,
                  const float* __restrict__ lng, const float* __restrict__ lnb,
                  float* __restrict__ xout,
                  float* __restrict__ cfin) {
    extern __shared__ float sm[];
    float* ws   = sm;
    float* hs   = sm + 8192;
    float* gT   = hs;
    float* hl   = sm + 24832;
    float* qs   = sm + 25856;
    float* ks_  = sm + 25920;
    float* vs   = sm + 25984;
    float* attn = sm + 26048;
    float* av   = sm + 26064;
    float* red  = sm + 26128;
    float* red2 = sm + 26160;

    const int tid  = threadIdx.x;
    const int cta  = blockIdx.x;
    const int wid  = tid >> 5, lane = tid & 31;
    const int n    = cta >> 5;
    const int g0   = cta * 32;
    const int b    = cta;

#pragma unroll
    for (int i = 0; i < 4; i++) {
        int id = i * 512 + tid;
        ((float4*)ws)[id] = ((const float4*)(Whh_l + (size_t)g0 * BS))[id];
    }

    g_h[cta * 512 + tid] = h0_l[cta * 512 + tid];

    float creg[2] = {0.f, 0.f};
    if (cta < 64) {
#pragma unroll
        for (int v = 0; v < 2; v++)
            creg[v] = c0_l[(size_t)b * NHID + v * 512 + tid];
    }
    grid_barrier();

    for (int t = 0; t < TT; t++) {
#pragma unroll
        for (int i = 0; i < 8; i++) {
            int id = i * 512 + tid;
            int bb = id >> 6, k4 = id & 63;
            float4 v = __ldcg((const float4*)&g_h[(size_t)bb * NHID + n * BS] + k4);
            int k = k4 * 4;
            hs[(k + 0) * 65 + bb] = v.x;
            hs[(k + 1) * 65 + bb] = v.y;
            hs[(k + 2) * 65 + bb] = v.z;
            hs[(k + 3) * 65 + bb] = v.w;
        }
        __syncthreads();

        float a00 = 0.f, a01 = 0.f, a10 = 0.f, a11 = 0.f;
        {
            const float4* w0 = (const float4*)(ws + (size_t)(2 * wid) * BS);
            const float4* w1 = (const float4*)(ws + (size_t)(2 * wid + 1) * BS);
#pragma unroll 8
            for (int k4 = 0; k4 < 64; k4++) {
                float4 x0 = w0[k4], x1 = w1[k4];
                int k = k4 * 4;
                float h0v = hs[(k + 0) * 65 + lane];
                float h1v = hs[(k + 1) * 65 + lane];
                float h2v = hs[(k + 2) * 65 + lane];
                float h3v = hs[(k + 3) * 65 + lane];
                float p0v = hs[(k + 0) * 65 + lane + 32];
                float p1v = hs[(k + 1) * 65 + lane + 32];
                float p2v = hs[(k + 2) * 65 + lane + 32];
                float p3v = hs[(k + 3) * 65 + lane + 32];
                a00 = fmaf(x0.x, h0v, a00); a00 = fmaf(x0.y, h1v, a00);
                a00 = fmaf(x0.z, h2v, a00); a00 = fmaf(x0.w, h3v, a00);
                a01 = fmaf(x1.x, h0v, a01); a01 = fmaf(x1.y, h1v, a01);
                a01 = fmaf(x1.z, h2v, a01); a01 = fmaf(x1.w, h3v, a01);
                a10 = fmaf(x0.x, p0v, a10); a10 = fmaf(x0.y, p1v, a10);
                a10 = fmaf(x0.z, p2v, a10); a10 = fmaf(x0.w, p3v, a10);
                a11 = fmaf(x1.x, p0v, a11); a11 = fmaf(x1.y, p1v, a11);
                a11 = fmaf(x1.z, p2v, a11); a11 = fmaf(x1.w, p3v, a11);
            }
        }
        __syncthreads();
        gT[(2 * wid) * 65 + lane]          = a00;
        gT[(2 * wid + 1) * 65 + lane]      = a01;
        gT[(2 * wid) * 65 + lane + 32]     = a10;
        gT[(2 * wid + 1) * 65 + lane + 32] = a11;
        __syncthreads();
#pragma unroll
        for (int i = 0; i < 4; i++) {
            int id = i * 512 + tid;
            int bb = id >> 5, gcol = id & 31;
            g_hh[(size_t)bb * G4 + g0 + gcol] = gT[gcol * 65 + bb];
        }
        grid_barrier();

        if (cta < 64) {
            const float* gih = gates + ((size_t)t * BB + b) * G4;
            const float* ghh = g_hh + (size_t)b * G4;
            float hv[2];
#pragma unroll
            for (int v = 0; v < 2; v++) {
                int idx = v * 512 + tid, nn2 = idx >> 8, ti = idx & 255;
                int base = nn2 * 1024 + ti;
                float ig = __ldcg(gih + base)       + __ldcg(ghh + base);
                float fg = __ldcg(gih + base + 256) + __ldcg(ghh + base + 256);
                float gg = __ldcg(gih + base + 512) + __ldcg(ghh + base + 512);
                float og = __ldcg(gih + base + 768) + __ldcg(ghh + base + 768);
                float cn = sigf(fg) * creg[v] + sigf(ig) * tanhf(gg);
                creg[v] = cn;
                hv[v] = sigf(og) * tanhf(cn);
                hl[idx] = hv[v];
            }
            __syncthreads();

            for (int s = tid; s < 768; s += 512) {
                int combo = s >> 2, q = s & 3;
                int p = combo / 64, r2 = combo % 64, nn2 = r2 >> 4, d = r2 & 15;
                const float* W = (p == 0 ? wq : (p == 1 ? wk : wv)) + (size_t)d * BS + q * 64;
                const float* H = hl + nn2 * 256 + q * 64;
                const float4* W4 = (const float4*)W;
                const float4* H4 = (const float4*)H;
                float sv = 0.f;
#pragma unroll
                for (int k4 = 0; k4 < 16; k4++) {
                    float4 w = W4[k4], hh2 = H4[k4];
                    sv += w.x * hh2.x + w.y * hh2.y + w.z * hh2.z + w.w * hh2.w;
                }
                sv += __shfl_down_sync(0xffffffffu, sv, 2);
                sv += __shfl_down_sync(0xffffffffu, sv, 1);
                if (q == 0) {
                    sv += (p == 0 ? bq : (p == 1 ? bk : bv))[d];
                    if (p == 0) qs[nn2 * 16 + d] = sv;
                    else if (p == 1) ks_[nn2 * 16 + d] = sv;
                    else vs[nn2 * 16 + d] = sv;
                }
            }
            __syncthreads();

            if (tid < 16) {
                int nn2 = tid >> 2, m = tid & 3;
                float sv = 0.f;
#pragma unroll
                for (int d = 0; d < DKq; d++) sv += qs[nn2 * 16 + d] * ks_[m * 16 + d];
                attn[nn2 * 4 + m] = sv * 0.25f;
            }
            __syncthreads();
            if (tid < 4) {
                float s0 = attn[tid * 4 + 0], s1 = attn[tid * 4 + 1];
                float s2 = attn[tid * 4 + 2], s3 = attn[tid * 4 + 3];
                float mx = fmaxf(fmaxf(s0, s1), fmaxf(s2, s3));
                float e0 = expf(s0 - mx), e1 = expf(s1 - mx);
                float e2 = expf(s2 - mx), e3 = expf(s3 - mx);
                float inv = 1.f / (e0 + e1 + e2 + e3);
                attn[tid * 4 + 0] = e0 * inv; attn[tid * 4 + 1] = e1 * inv;
                attn[tid * 4 + 2] = e2 * inv; attn[tid * 4 + 3] = e3 * inv;
            }
            __syncthreads();
            if (tid < 64) {
                int nn2 = tid >> 4, d = tid & 15;
                av[nn2 * 16 + d] = attn[nn2 * 4 + 0] * vs[0 * 16 + d] +
                                   attn[nn2 * 4 + 1] * vs[1 * 16 + d] +
                                   attn[nn2 * 4 + 2] * vs[2 * 16 + d] +
                                   attn[nn2 * 4 + 3] * vs[3 * 16 + d];
            }
            __syncthreads();

            float val[2];
#pragma unroll
            for (int v = 0; v < 2; v++) {
                int idx = v * 512 + tid, nn2 = idx >> 8, ti = idx & 255;
                float w[DKq];
                const float4* wr = (const float4*)&wfc[(size_t)ti * DKq];
#pragma unroll
                for (int q4 = 0; q4 < 4; q4++) {
                    float4 vv = wr[q4];
                    w[q4 * 4 + 0] = vv.x; w[q4 * 4 + 1] = vv.y;
                    w[q4 * 4 + 2] = vv.z; w[q4 * 4 + 3] = vv.w;
                }
                float o = bfc[ti];
#pragma unroll
                for (int d = 0; d < DKq; d++) o += av[nn2 * 16 + d] * w[d];
                val[v] = o + hv[v];

                float s1 = val[v], sq = val[v] * val[v];
#pragma unroll
                for (int off = 16; off; off >>= 1) {
                    s1 += __shfl_down_sync(0xffffffffu, s1, off);
                    sq += __shfl_down_sync(0xffffffffu, sq, off);
                }
                if (lane == 0) {
                    int gw = (tid >> 5) & 7;
                    red[nn2 * 8 + gw]  = s1;
                    red2[nn2 * 8 + gw] = sq;
                }
            }
            __syncthreads();
            if (tid < 4) {
                float S = 0.f, S2 = 0.f;
#pragma unroll
                for (int w2 = 0; w2 < 8; w2++) {
                    S  += red[tid * 8 + w2];
                    S2 += red2[tid * 8 + w2];
                }
                red[tid * 8]  = S * (1.f / 256.f);
                red2[tid * 8] = S2 * (1.f / 256.f);
            }
            __syncthreads();
#pragma unroll
            for (int v = 0; v < 2; v++) {
                int idx = v * 512 + tid, nn2 = idx >> 8, ti = idx & 255;
                float mu = red[nn2 * 8];
                float var = red2[nn2 * 8] - mu * mu;
                float y = (val[v] - mu) * rsqrtf(var + 1e-5f) * lng[ti] + lnb[ti];
                g_h[(size_t)b * NHID + idx] = y;
                xout[((size_t)t * BB + b) * NHID + idx] = y;
            }
        }
        grid_barrier();
    }

    if (cta < 64) {
#pragma unroll
        for (int v = 0; v < 2; v++)
            cfin[(size_t)b * NHID + v * 512 + tid] = creg[v];
    }
}

// ---------------- host orchestration ----------------
extern "C" void kernel_launch(void* const* d_in, const int* in_sizes, int n_in,
                              void* d_out, int out_size) {
    (void)in_sizes; (void)n_in; (void)out_size;
    const int*   tokens = (const int*)d_in[0];
    const float* h0     = (const float*)d_in[1];
    const float* c0     = (const float*)d_in[2];
    const float* embW   = (const float*)d_in[3];
    const float* Wih    = (const float*)d_in[4];
    const float* Whh    = (const float*)d_in[5];
    const float* bih    = (const float*)d_in[6];
    const float* bhh    = (const float*)d_in[7];
    const float* wq     = (const float*)d_in[8];
    const float* bq     = (const float*)d_in[9];
    const float* wk     = (const float*)d_in[10];
    const float* bk     = (const float*)d_in[11];
    const float* wv     = (const float*)d_in[12];
    const float* bv     = (const float*)d_in[13];
    const float* wfc    = (const float*)d_in[14];
    const float* bfc    = (const float*)d_in[15];
    const float* lng    = (const float*)d_in[16];
    const float* lnb    = (const float*)d_in[17];
    const float* decW   = (const float*)d_in[18];
    const float* decb   = (const float*)d_in[19];
    float* out = (float*)d_out;

    float *xa, *xb, *gates, *hsym;
    __nv_bfloat16 *a0, *a1, *a2, *w0, *w1, *w2, *dh, *dl;
    cudaGetSymbolAddress((void**)&xa, g_xa);
    cudaGetSymbolAddress((void**)&xb, g_xb);
    cudaGetSymbolAddress((void**)&gates, g_gates);
    cudaGetSymbolAddress((void**)&hsym, g_h);
    cudaGetSymbolAddress((void**)&a0, g_a0);
    cudaGetSymbolAddress((void**)&a1, g_a1);
    cudaGetSymbolAddress((void**)&a2, g_a2);
    cudaGetSymbolAddress((void**)&w0, g_w0);
    cudaGetSymbolAddress((void**)&w1, g_w1);
    cudaGetSymbolAddress((void**)&w2, g_w2);
    cudaGetSymbolAddress((void**)&dh, g_dh);
    cudaGetSymbolAddress((void**)&dl, g_dl);

    cudaFuncSetAttribute(recur_kernel,
                         cudaFuncAttributeMaxDynamicSharedMemorySize, RSM_BYTES);
    cudaFuncSetAttribute(mma_gemm_ih,
                         cudaFuncAttributeMaxDynamicSharedMemorySize, IH_SMEM_BYTES);
    cudaFuncSetAttribute(mma_gemm_dec,
                         cudaFuncAttributeMaxDynamicSharedMemorySize, DEC_SMEM_BYTES);

    const size_t stateN = (size_t)BB * NHID;
    const size_t decN   = (size_t)TT * BB * NTOK;
    const int xN4 = TT * BB * NHID / 4;

    embed_kernel<<<TT * BB, 256>>>(tokens, embW, xa);

    float* xin = xa;
    float* xo  = xb;
    for (int l = 0; l < NLAYERS; l++) {
        split3_kernel<<<512, 256>>>(xin, a0, a1, a2, xN4);
        split3_kernel<<<512, 256>>>(Wih + (size_t)l * G4 * NHID, w0, w1, w2,
                                    G4 * NHID / 4);
        mma_gemm_ih<<<dim3((TT * BB) / 128, G4 / 128), 256, IH_SMEM_BYTES>>>(
            a0, a1, a2, w0, w1, w2, gates,
            TT * BB, G4, NHID, bih + (size_t)l * G4, bhh + (size_t)l * G4);

        recur_kernel<<<RK_CTAS, 512, RSM_BYTES>>>(
            gates, Whh + (size_t)l * G4 * BS,
            h0 + (size_t)l * stateN, c0 + (size_t)l * stateN,
            wq, bq, wk, bk, wv, bv, wfc, bfc, lng, lnb,
            xo, out + decN + 2 * stateN + (size_t)l * stateN);

        cudaMemcpyAsync(out + decN + (size_t)l * stateN, hsym,
                        stateN * sizeof(float), cudaMemcpyDeviceToDevice, 0);

        float* tmp = xin; xin = xo; xo = tmp;
    }

    // decoder: pre-split A (x) and B (decW), then bf16 GEMM
    split2_kernel<<<512, 256>>>(xin, a0, a1, xN4);
    split2_kernel<<<2048, 256>>>(decW, dh, dl, NTOK * NHID / 4);
    mma_gemm_dec<<<dim3((TT * BB) / 128, NTOK / 128), 256, DEC_SMEM_BYTES>>>(
        a0, a1, dh, dl, out, TT * BB, NTOK, NHID, decb);
}